// round 14
// baseline (speedup 1.0000x reference)
#include <cuda_runtime.h>

#define B_ 4
#define C_ 32
#define H_ 512
#define W_ 512

// ---------------- scratch (device globals; no runtime allocation) ----------------
static __device__ float g_s1[(size_t)B_ * C_ * 256 * 256];
static __device__ float g_s2[(size_t)B_ * C_ * 256 * 256];
static __device__ float g_q1[(size_t)B_ * C_ * 128 * 128];
static __device__ float g_q2[(size_t)B_ * C_ * 128 * 128];
static __device__ float g_e1[(size_t)B_ * C_ * 64 * 64];
static __device__ float g_e2[(size_t)B_ * C_ * 64 * 64];
static __device__ float g_partS[20 * 8192];
static __device__ float g_partQ[20 * 8192];
static __device__ float g_norm[40];                         // (mean, inv_std) per (b, branch)
static __device__ float g_keff[(size_t)B_ * 32 * 25 * 32];  // composed 5x5 kernels [b][ci][tap][co]
static __device__ float g_c1[B_ * 32];                      // conv1 constant term
static __device__ float g_ws[160];                          // sum of w1 over (ci,taps): [co][br]
static __device__ float g_w3x3[3 * 9216];                   // transposed [ci][tap][co] for w2..w4
static __device__ float g_ck[3 * 16384];                    // composed deconv+conv: [st][ci][phw][cell][co]
static __device__ float g_cb[96];                           // composed bias per stage [st][co]

// ---------------- packed f32x2 helpers ----------------
typedef unsigned long long u64;

__device__ __forceinline__ u64 pk(float v) {
    u64 r; asm("mov.b64 %0, {%1, %1};" : "=l"(r) : "f"(v)); return r;
}
__device__ __forceinline__ u64 pk2(float a, float b) {
    u64 r; asm("mov.b64 %0, {%1, %2};" : "=l"(r) : "f"(a), "f"(b)); return r;
}
__device__ __forceinline__ void fma2(u64& d, u64 a, u64 b) {
    asm("fma.rn.f32x2 %0, %1, %2, %0;" : "+l"(d) : "l"(a), "l"(b));
}
__device__ __forceinline__ void unpk(u64 v, float& lo, float& hi) {
    asm("mov.b64 {%0, %1}, %2;" : "=f"(lo), "=f"(hi) : "l"(v));
}

// ---------------- cp.async helpers ----------------
__device__ __forceinline__ unsigned scvt(const void* p) {
    return (unsigned)__cvta_generic_to_shared(p);
}
__device__ __forceinline__ void cpa4f(unsigned s, const float* g) {
    asm volatile("cp.async.ca.shared.global [%0], [%1], 4;" :: "r"(s), "l"(g));
}
__device__ __forceinline__ void cpa16(unsigned s, const float* g, bool ok) {
    asm volatile("cp.async.cg.shared.global [%0], [%1], 16, %2;"
                 :: "r"(s), "l"(g), "r"(ok ? 16 : 0));
}
__device__ __forceinline__ void cpa16f(unsigned s, const float* g) {
    asm volatile("cp.async.cg.shared.global [%0], [%1], 16;" :: "r"(s), "l"(g));
}
#define CP_COMMIT() asm volatile("cp.async.commit_group;" ::: "memory")
#define CP_WAIT0()  asm volatile("cp.async.wait_group 0;" ::: "memory")

// ---------------- shared edge-operator math ----------------
__device__ __forceinline__ void edge5(float a00, float a01, float a02,
                                      float a10, float a11, float a12,
                                      float a20, float a21, float a22, float o[5]) {
    float sxv = -a00 + a02 - 2.f * a10 + 2.f * a12 - a20 + a22;
    float syv = -a00 - 2.f * a01 - a02 + a20 + 2.f * a21 + a22;
    o[0] = 0.5f * (sxv + syv);
    float cxv = -3.f * a00 + 3.f * a02 - 10.f * a10 + 10.f * a12 - 3.f * a20 + 3.f * a22;
    float cyv = -3.f * a00 - 10.f * a01 - 3.f * a02 + 3.f * a20 + 10.f * a21 + 3.f * a22;
    o[1] = 0.5f * (cxv + cyv);
    o[2] = 2.f * a00 + 2.f * a02 - 8.f * a11 + 2.f * a20 + 2.f * a22;
    o[3] = 0.5f * ((-a00 + a11) + (-a01 + a10));
    float pxv = a00 + a01 + a02 - a20 - a21 - a22;
    float pyv = -a00 + a02 - a10 + a12 - a20 + a22;
    o[4] = 0.5f * (pxv + pyv);
}

static __device__ const float G_[5][3][3] = {
    {{-1.f, -1.f, 0.f}, {-1.f, 0.f, 1.f}, {0.f, 1.f, 1.f}},
    {{-3.f, -5.f, 0.f}, {-5.f, 0.f, 5.f}, {0.f, 5.f, 3.f}},
    {{2.f, 0.f, 2.f}, {0.f, -8.f, 0.f}, {2.f, 0.f, 2.f}},
    {{-0.5f, -0.5f, 0.f}, {0.5f, 0.5f, 0.f}, {0.f, 0.f, 0.f}},
    {{0.f, 0.5f, 1.f}, {-0.5f, 0.f, 0.5f}, {-1.f, -0.5f, 0.f}}
};

__device__ __forceinline__ int refl(int i, int n) {
    return i < 0 ? -i : (i >= n ? 2 * n - 2 - i : i);
}

// ---------------- fused operator + partial stats (4 px/thread) ----------------
__global__ void stats_op_kernel(const float* __restrict__ x) {
    __shared__ float sx[34 * 34];
    __shared__ float red[8][10];
    const int tx = threadIdx.x, ty = threadIdx.y;
    const int tid = ty * 32 + tx;
    const int w0 = blockIdx.x * 32, h0 = blockIdx.y * 32;
    const int bc = blockIdx.z;
    const int b = bc >> 5, c = bc & 31;
    const float* xp = x + (size_t)bc * H_ * W_;

    for (int i = tid; i < 1156; i += 256) {
        int r = i / 34, cl = i - r * 34;
        sx[i] = xp[refl(h0 - 1 + r, H_) * W_ + refl(w0 - 1 + cl, W_)];
    }
    __syncthreads();

    float s[5] = {0.f, 0.f, 0.f, 0.f, 0.f}, q[5] = {0.f, 0.f, 0.f, 0.f, 0.f};
#pragma unroll
    for (int k = 0; k < 4; ++k) {
        const int r = ty * 4 + k;
        float o[5];
        edge5(sx[r * 34 + tx], sx[r * 34 + tx + 1], sx[r * 34 + tx + 2],
              sx[(r + 1) * 34 + tx], sx[(r + 1) * 34 + tx + 1], sx[(r + 1) * 34 + tx + 2],
              sx[(r + 2) * 34 + tx], sx[(r + 2) * 34 + tx + 1], sx[(r + 2) * 34 + tx + 2], o);
#pragma unroll
        for (int br = 0; br < 5; ++br) {
            s[br] += o[br];
            q[br] += o[br] * o[br];
        }
    }

#pragma unroll
    for (int br = 0; br < 5; ++br) {
        float sv = s[br], qv = q[br];
#pragma unroll
        for (int off = 16; off; off >>= 1) {
            sv += __shfl_down_sync(0xffffffffu, sv, off);
            qv += __shfl_down_sync(0xffffffffu, qv, off);
        }
        if (tx == 0) { red[ty][br] = sv; red[ty][5 + br] = qv; }
    }
    __syncthreads();
    if (tid < 10) {
        float t = 0.f;
#pragma unroll
        for (int w = 0; w < 8; ++w) t += red[w][tid];
        int tile = blockIdx.x + 16 * blockIdx.y + 256 * c;
        if (tid < 5) g_partS[(b * 5 + tid) * 8192 + tile] = t;
        else         g_partQ[(b * 5 + tid - 5) * 8192 + tile] = t;
    }
}

// stage2 (blocks 0-19) + w1 sums (block 20)
__global__ void stats2_kernel(const float* __restrict__ w1) {
    if (blockIdx.x == 20) {
        int t = threadIdx.x;
        if (t < 160) {
            int co = t / 5, br = t % 5;
            float s = 0.f;
            for (int ci = 0; ci < 32; ++ci) {
                const float* wq = &w1[((size_t)co * 160 + br * 32 + ci) * 9];
#pragma unroll
                for (int u = 0; u < 9; ++u) s += wq[u];
            }
            g_ws[t] = s;
        }
        return;
    }
    __shared__ float rs[256], rq[256];
    const int seg = blockIdx.x, t = threadIdx.x;
    float s = 0.f, q = 0.f;
    for (int i = t; i < 8192; i += 256) {
        s += g_partS[seg * 8192 + i];
        q += g_partQ[seg * 8192 + i];
    }
    rs[t] = s; rq[t] = q;
    __syncthreads();
    for (int st = 128; st > 0; st >>= 1) {
        if (t < st) { rs[t] += rs[t + st]; rq[t] += rq[t + st]; }
        __syncthreads();
    }
    if (t == 0) {
        const double N = (double)32 * H_ * W_;
        double mean = (double)rs[0] / N;
        double var = (double)rq[0] / N - mean * mean;
        if (var < 1e-30) var = 1e-30;
        g_norm[seg * 2 + 0] = (float)mean;
        g_norm[seg * 2 + 1] = (float)(1.0 / sqrt(var));
    }
}

// ---------------- weight prep: transpose w2..w4 ----------------
__global__ void prep_w_kernel(const float* w2, const float* w3, const float* w4) {
    const float* src[3] = {w2, w3, w4};
    const float* s = src[blockIdx.x];
    float* dst = g_w3x3 + blockIdx.x * 9216;
    for (int i = threadIdx.x; i < 9216; i += 256) {
        int ci = i / 288, rem = i - ci * 288;
        int tap = rem >> 5, co = rem & 31;
        dst[i] = s[((size_t)co * 32 + ci) * 9 + tap];
    }
}

// keff (ci < 32) + c1 constant (ci == 32)
__global__ void keff_kernel(const float* __restrict__ w1, const float* __restrict__ b1) {
    const int b = blockIdx.x, ci = blockIdx.y, co = threadIdx.x;
    if (ci == 32) {
        float s = b1[co];
#pragma unroll
        for (int br = 0; br < 5; ++br) {
            float m = g_norm[(b * 5 + br) * 2], ns = g_norm[(b * 5 + br) * 2 + 1];
            s -= m * ns * g_ws[co * 5 + br];
        }
        g_c1[b * 32 + co] = s;
        return;
    }
    float k[25];
#pragma unroll
    for (int t = 0; t < 25; ++t) k[t] = 0.f;
#pragma unroll
    for (int br = 0; br < 5; ++br) {
        float ns = g_norm[(b * 5 + br) * 2 + 1];
#pragma unroll
        for (int ui = 0; ui < 3; ++ui)
#pragma unroll
            for (int uj = 0; uj < 3; ++uj) {
                float wv = ns * w1[(((size_t)co * 160 + br * 32 + ci) * 3 + ui) * 3 + uj];
#pragma unroll
                for (int vi = 0; vi < 3; ++vi)
#pragma unroll
                    for (int vj = 0; vj < 3; ++vj)
                        k[(ui + vi) * 5 + (uj + vj)] += wv * G_[br][vi][vj];
            }
    }
    for (int t = 0; t < 25; ++t)
        g_keff[(((size_t)b * 32 + ci) * 25 + t) * 32 + co] = k[t];
}

// ---------------- composed deconv2x2(s2)+conv3x3 weights ----------------
__global__ void ck_kernel(const float* dw1, const float* db1, const float* w5, const float* b5,
                          const float* dw2, const float* db2, const float* w6, const float* b6,
                          const float* dw3, const float* db3, const float* w7, const float* b7) {
    const int st = blockIdx.y;
    const float* dw = st == 0 ? dw1 : st == 1 ? dw2 : dw3;
    const float* db = st == 0 ? db1 : st == 1 ? db2 : db3;
    const float* cw = st == 0 ? w5 : st == 1 ? w6 : w7;
    const float* cb = st == 0 ? b5 : st == 1 ? b6 : b7;
    const int ci = blockIdx.x, co = threadIdx.x;
    if (ci == 32) {
        float s = cb[co];
        for (int m = 0; m < 32; ++m) {
            float ws = 0.f;
#pragma unroll
            for (int t = 0; t < 9; ++t) ws += cw[((size_t)co * 32 + m) * 9 + t];
            s += db[m] * ws;
        }
        g_cb[st * 32 + co] = s;
        return;
    }
    float K[4][4];
#pragma unroll
    for (int i = 0; i < 4; ++i)
#pragma unroll
        for (int j = 0; j < 4; ++j) K[i][j] = 0.f;
    for (int m = 0; m < 32; ++m) {
        float dv[2][2];
#pragma unroll
        for (int pp = 0; pp < 2; ++pp)
#pragma unroll
            for (int qq = 0; qq < 2; ++qq)
                dv[pp][qq] = dw[(((size_t)ci * 32 + m) * 2 + pp) * 2 + qq];
        const float* cwm = &cw[((size_t)co * 32 + m) * 9];
#pragma unroll
        for (int ph = 0; ph < 2; ++ph)
#pragma unroll
            for (int pw = 0; pw < 2; ++pw)
#pragma unroll
                for (int di = 0; di < 3; ++di) {
                    int sh = di + 1 - ph, r = sh >> 1, pp = sh & 1;
#pragma unroll
                    for (int dj = 0; dj < 3; ++dj) {
                        int sw = dj + 1 - pw, c = sw >> 1, qq = sw & 1;
                        K[ph * 2 + pw][r * 2 + c] += dv[pp][qq] * cwm[di * 3 + dj];
                    }
                }
    }
#pragma unroll
    for (int phw = 0; phw < 4; ++phw)
#pragma unroll
        for (int cell = 0; cell < 4; ++cell)
            g_ck[st * 16384 + ((ci * 4 + phw) * 4 + cell) * 32 + co] = K[phw][cell];
}

// ---------------- conv1 interior: composed 5x5 conv + fused pool ----------------
__global__ void __launch_bounds__(256, 3)
conv1_5x5_kernel(const float* __restrict__ x, float* __restrict__ out) {
    constexpr int CH = 1728;
    __shared__ __align__(16) float s_x[2][CH];
    __shared__ __align__(16) float s_w[2][3200];
    const int tx = threadIdx.x, ty = threadIdx.y, tid = ty * 32 + tx;
    const int w0 = 2 + blockIdx.x * 32, h0 = 2 + blockIdx.y * 8;
    const int b = blockIdx.z;
    const int gr = ty & 3, ch = ty >> 2;
    const bool fast = (blockIdx.x < 15) && (blockIdx.y < 63);

    auto issue = [&](int ci0, int buf) {
        const float* kw = g_keff + (size_t)(b * 32 + ci0) * 800;
        if (fast) {
#pragma unroll
            for (int k = 0; k < 5; ++k) {
                int i = tid + k * 256;
                if (i < 432) {
                    int cc = i / 108, rem = i - cc * 108;
                    int r = rem / 9, p = rem - r * 9;
                    cpa16f(scvt(&s_x[buf][cc * 432 + r * 36 + p * 4]),
                           &x[((size_t)(b * 32 + ci0 + cc) * 512 + (h0 - 2 + r)) * 512 + (w0 - 2) + p * 4]);
                } else if (i < 1232) {
                    int j = i - 432;
                    cpa16f(scvt(&s_w[buf][j * 4]), kw + j * 4);
                }
            }
        } else {
#pragma unroll
            for (int k = 0; k < 7; ++k) {
                int i = tid + k * 256;
                if (i < CH) {
                    int cc = i / 432, rem = i - cc * 432;
                    int r = rem / 36, cl = rem - r * 36;
                    cpa4f(scvt(&s_x[buf][i]),
                          &x[((size_t)(b * 32 + ci0 + cc) * 512 + refl(h0 - 2 + r, 512)) * 512 + refl(w0 - 2 + cl, 512)]);
                }
            }
#pragma unroll
            for (int k = 0; k < 4; ++k) {
                int i = tid + k * 256;
                if (i < 800)
                    cpa16f(scvt(&s_w[buf][i * 4]), kw + i * 4);
            }
        }
    };
    issue(0, 0);
    CP_COMMIT();

    u64 acc[2][8];
#pragma unroll
    for (int j = 0; j < 8; ++j) {
        u64 cv = pk2(g_c1[b * 32 + ch * 16 + 2 * j], g_c1[b * 32 + ch * 16 + 2 * j + 1]);
        acc[0][j] = cv; acc[1][j] = cv;
    }

    int buf = 0;
    for (int ci0 = 0; ci0 < 32; ci0 += 4) {
        CP_WAIT0();
        __syncthreads();
        if (ci0 + 4 < 32) { issue(ci0 + 4, buf ^ 1); CP_COMMIT(); }
#pragma unroll
        for (int cc = 0; cc < 4; ++cc) {
            const float* ib = &s_x[buf][cc * 432 + (gr * 2) * 36 + tx];
            const float* wb = &s_w[buf][cc * 800];
            // rolling row cache: rows 0..5, 5 floats each, loaded once
            float rowf[2][5];
#pragma unroll
            for (int tj = 0; tj < 5; ++tj) rowf[0][tj] = ib[tj];
#pragma unroll
            for (int ti = 0; ti < 5; ++ti) {
                const float* nr = ib + (ti + 1) * 36;
#pragma unroll
                for (int tj = 0; tj < 5; ++tj) rowf[(ti + 1) & 1][tj] = nr[tj];
#pragma unroll
                for (int tj = 0; tj < 5; ++tj) {
                    u64 v0 = pk(rowf[ti & 1][tj]);
                    u64 v1 = pk(rowf[(ti + 1) & 1][tj]);
                    const u64* wq = (const u64*)(wb + (ti * 5 + tj) * 32) + ch * 8;
                    u64 q0 = wq[0], q1 = wq[1], q2 = wq[2], q3 = wq[3];
                    u64 q4 = wq[4], q5 = wq[5], q6 = wq[6], q7 = wq[7];
                    fma2(acc[0][0], v0, q0); fma2(acc[0][1], v0, q1);
                    fma2(acc[0][2], v0, q2); fma2(acc[0][3], v0, q3);
                    fma2(acc[0][4], v0, q4); fma2(acc[0][5], v0, q5);
                    fma2(acc[0][6], v0, q6); fma2(acc[0][7], v0, q7);
                    fma2(acc[1][0], v1, q0); fma2(acc[1][1], v1, q1);
                    fma2(acc[1][2], v1, q2); fma2(acc[1][3], v1, q3);
                    fma2(acc[1][4], v1, q4); fma2(acc[1][5], v1, q5);
                    fma2(acc[1][6], v1, q6); fma2(acc[1][7], v1, q7);
                }
            }
        }
        buf ^= 1;
    }

    const int hp = (h0 >> 1) + gr;
    const int wp = (w0 + tx) >> 1;
    const size_t plane = 65536;
    size_t ob = ((size_t)b * 32 + ch * 16) * plane + (size_t)hp * 256 + wp;
    const bool st = ((tx & 1) == 0) && hp < 255 && wp < 255;
#pragma unroll
    for (int j = 0; j < 8; ++j) {
        float l0, u0, l1, u1;
        unpk(acc[0][j], l0, u0);
        unpk(acc[1][j], l1, u1);
        float m0 = fmaxf(l0, l1), m1 = fmaxf(u0, u1);
        m0 = fmaxf(m0, __shfl_xor_sync(0xffffffffu, m0, 1));
        m1 = fmaxf(m1, __shfl_xor_sync(0xffffffffu, m1, 1));
        if (st) {
            out[ob + (size_t)(2 * j) * plane] = m0;
            out[ob + (size_t)(2 * j + 1) * plane] = m1;
        }
    }
}

// ---------------- conv1 border strips (2 conv rows/cols only) ----------------
__global__ void __launch_bounds__(256, 2)
conv1_strip_kernel(const float* __restrict__ x, const float* __restrict__ wgt,
                   const float* __restrict__ bias, float* __restrict__ out) {
    __shared__ __align__(16) float s_x[2][216];
    __shared__ __align__(16) float s_op[5][136];
    __shared__ __align__(16) float s_w[2][1440];
    __shared__ float s_nm[5], s_ns[5];
    const int tx = threadIdx.x, ty = threadIdx.y, tid = ty * 32 + tx;
    const int b = blockIdx.y;
    int si = blockIdx.x;
    const bool vert = si >= 32;
    si &= 31;
    const int longB = (si & 15) * 32;
    const int shortB = (si < 16) ? 0 : 510;

    if (tid < 5) {
        s_nm[tid] = g_norm[(b * 5 + tid) * 2 + 0];
        s_ns[tid] = g_norm[(b * 5 + tid) * 2 + 1];
    }

    if (tid < 216) {
        int r = tid / 36, c = tid - r * 36;
        int gh = vert ? (longB - 2 + c) : (shortB - 2 + r);
        int gw = vert ? (shortB - 2 + r) : (longB - 2 + c);
        s_x[0][tid] = x[((size_t)b * 32 * 512 + refl(gh, 512)) * 512 + refl(gw, 512)];
    }
#pragma unroll
    for (int k = 0; k < 6; ++k) {
        int i = tid + k * 256;
        if (i < 1440) {
            int br = i / 288, rem = i - br * 288;
            int tap = rem >> 5, co = rem & 31;
            s_w[0][i] = wgt[((size_t)co * 160 + br * 32) * 9 + tap];
        }
    }
    __syncthreads();

    u64 acc[2][2];
#pragma unroll
    for (int q = 0; q < 2; ++q) {
        u64 bv = pk2(bias[ty * 4 + 2 * q], bias[ty * 4 + 2 * q + 1]);
        acc[0][q] = bv; acc[1][q] = bv;
    }

    int buf = 0;
    for (int ci = 0; ci < 32; ++ci) {
        const bool more = (ci + 1 < 32);
        float rx, rw[6];
        if (more) {
            if (tid < 216) {
                int r = tid / 36, c = tid - r * 36;
                int gh = vert ? (longB - 2 + c) : (shortB - 2 + r);
                int gw = vert ? (shortB - 2 + r) : (longB - 2 + c);
                rx = x[(((size_t)b * 32 + ci + 1) * 512 + refl(gh, 512)) * 512 + refl(gw, 512)];
            }
#pragma unroll
            for (int k = 0; k < 6; ++k) {
                int i = tid + k * 256;
                if (i < 1440) {
                    int br = i / 288, rem = i - br * 288;
                    int tap = rem >> 5, co = rem & 31;
                    rw[k] = wgt[((size_t)co * 160 + br * 32 + ci + 1) * 9 + tap];
                }
            }
        }
        if (tid < 136) {
            int sp = tid / 34, lp = tid - sp * 34;
            int h = vert ? (longB - 1 + lp) : (shortB - 1 + sp);
            int w = vert ? (shortB - 1 + sp) : (longB - 1 + lp);
            float o[5] = {0.f, 0.f, 0.f, 0.f, 0.f};
            if (h >= 0 && h < 512 && w >= 0 && w < 512) {
                float a[3][3];
#pragma unroll
                for (int dh = 0; dh < 3; ++dh)
#pragma unroll
                    for (int dw = 0; dw < 3; ++dw) {
                        int r = vert ? (sp + dw) : (sp + dh);
                        int c = vert ? (lp + dh) : (lp + dw);
                        a[dh][dw] = s_x[buf][r * 36 + c];
                    }
                edge5(a[0][0], a[0][1], a[0][2], a[1][0], a[1][1], a[1][2],
                      a[2][0], a[2][1], a[2][2], o);
#pragma unroll
                for (int k = 0; k < 5; ++k) o[k] = (o[k] - s_nm[k]) * s_ns[k];
            }
#pragma unroll
            for (int k = 0; k < 5; ++k) s_op[k][tid] = o[k];
        }
        __syncthreads();

#pragma unroll
        for (int br = 0; br < 5; ++br) {
#pragma unroll
            for (int ds = 0; ds < 3; ++ds)
#pragma unroll
                for (int dl = 0; dl < 3; ++dl) {
                    int tap = vert ? (dl * 3 + ds) : (ds * 3 + dl);
                    const u64* wq = (const u64*)(&s_w[buf][br * 288 + tap * 32]) + ty * 2;
                    u64 q0 = wq[0], q1 = wq[1];
#pragma unroll
                    for (int s = 0; s < 2; ++s) {
                        u64 v = pk(s_op[br][(s + ds) * 34 + tx + dl]);
                        fma2(acc[s][0], v, q0);
                        fma2(acc[s][1], v, q1);
                    }
                }
        }
        if (more) {
            if (tid < 216) s_x[buf ^ 1][tid] = rx;
#pragma unroll
            for (int k = 0; k < 6; ++k) {
                int i = tid + k * 256;
                if (i < 1440) s_w[buf ^ 1][i] = rw[k];
            }
        }
        __syncthreads();
        buf ^= 1;
    }

    const size_t plane = 65536;
    const int hp = vert ? ((longB + tx) >> 1) : (shortB >> 1);
    const int wp = vert ? (shortB >> 1) : ((longB + tx) >> 1);
#pragma unroll
    for (int q = 0; q < 2; ++q) {
        float l0, u0, l1, u1;
        unpk(acc[0][q], l0, u0);
        unpk(acc[1][q], l1, u1);
        float m0 = fmaxf(l0, l1), m1 = fmaxf(u0, u1);
        m0 = fmaxf(m0, __shfl_xor_sync(0xffffffffu, m0, 1));
        m1 = fmaxf(m1, __shfl_xor_sync(0xffffffffu, m1, 1));
        if (!(tx & 1)) {
            int co = ty * 4 + 2 * q;
            out[((size_t)(b * 32 + co) * plane) + (size_t)hp * 256 + wp] = m0;
            out[((size_t)(b * 32 + co + 1) * plane) + (size_t)hp * 256 + wp] = m1;
        }
    }
}

// ---------------- conv3x3 CIN=32 (zero pad), 16B cp.async pipelined ----------------
// MODE 0: plain; 1: fused pool
template <int MODE>
__global__ void __launch_bounds__(256, 3)
conv3x3_kernel(const float* __restrict__ in, const float* __restrict__ wgt,
               const float* __restrict__ bias, float* __restrict__ out,
               int Hh, int Ww) {
    constexpr int ROWW = 40;
    constexpr int CH = 4 * 10 * ROWW;
    __shared__ __align__(16) float s_in[2][CH];
    __shared__ __align__(16) float s_w[9216];
    const int tx = threadIdx.x, ty = threadIdx.y, tid = ty * 32 + tx;
    const int w0 = blockIdx.x * 32, h0 = blockIdx.y * 8;
    const int b = blockIdx.z;
    const int gr = ty & 3, ch = ty >> 2;

    {
        const float* g = wgt + tid * 4;
        unsigned sdst = scvt(&s_w[tid * 4]);
#pragma unroll
        for (int k = 0; k < 9; ++k) cpa16f(sdst + k * 4096, g + k * 1024);
    }
    auto issue = [&](int ci0, int buf) {
#pragma unroll
        for (int k = 0; k < 2; ++k) {
            int i = tid + k * 256;
            if (i < 400) {
                int cc = i / 100, rem = i - cc * 100;
                int r = rem / 10, pi = rem - r * 10;
                int gh = h0 - 1 + r;
                int gw0 = w0 - 4 + pi * 4;
                bool ok = (gh >= 0 && gh < Hh && gw0 >= 0 && gw0 + 4 <= Ww);
                const float* g = ok ? &in[(((size_t)b * 32 + ci0 + cc) * Hh + gh) * Ww + gw0] : in;
                cpa16(scvt(&s_in[buf][cc * 400 + r * ROWW + pi * 4]), g, ok);
            }
        }
    };
    issue(0, 0);
    CP_COMMIT();

    u64 acc[2][8];
#pragma unroll
    for (int j = 0; j < 8; ++j) {
        u64 bv = pk2(bias[ch * 16 + 2 * j], bias[ch * 16 + 2 * j + 1]);
        acc[0][j] = bv; acc[1][j] = bv;
    }

    int buf = 0;
    for (int ci0 = 0; ci0 < 32; ci0 += 4) {
        CP_WAIT0();
        __syncthreads();
        if (ci0 + 4 < 32) { issue(ci0 + 4, buf ^ 1); CP_COMMIT(); }
#pragma unroll
        for (int cc = 0; cc < 4; ++cc) {
            const float* ib = &s_in[buf][cc * 400 + (gr * 2) * ROWW + tx + 3];
            const float* wb = &s_w[(ci0 + cc) * 288];
            // rolling row cache: rows 0..3, 3 floats each
            float rowf[2][3];
#pragma unroll
            for (int tj = 0; tj < 3; ++tj) rowf[0][tj] = ib[tj];
#pragma unroll
            for (int di = 0; di < 3; ++di) {
                const float* nr = ib + (di + 1) * ROWW;
#pragma unroll
                for (int tj = 0; tj < 3; ++tj) rowf[(di + 1) & 1][tj] = nr[tj];
#pragma unroll
                for (int dj = 0; dj < 3; ++dj) {
                    u64 v0 = pk(rowf[di & 1][dj]);
                    u64 v1 = pk(rowf[(di + 1) & 1][dj]);
                    const u64* wq = (const u64*)(wb + (di * 3 + dj) * 32) + ch * 8;
                    u64 q0 = wq[0], q1 = wq[1], q2 = wq[2], q3 = wq[3];
                    u64 q4 = wq[4], q5 = wq[5], q6 = wq[6], q7 = wq[7];
                    fma2(acc[0][0], v0, q0); fma2(acc[0][1], v0, q1);
                    fma2(acc[0][2], v0, q2); fma2(acc[0][3], v0, q3);
                    fma2(acc[0][4], v0, q4); fma2(acc[0][5], v0, q5);
                    fma2(acc[0][6], v0, q6); fma2(acc[0][7], v0, q7);
                    fma2(acc[1][0], v1, q0); fma2(acc[1][1], v1, q1);
                    fma2(acc[1][2], v1, q2); fma2(acc[1][3], v1, q3);
                    fma2(acc[1][4], v1, q4); fma2(acc[1][5], v1, q5);
                    fma2(acc[1][6], v1, q6); fma2(acc[1][7], v1, q7);
                }
            }
        }
        buf ^= 1;
    }

    if (MODE == 1) {
        const int Hp = Hh >> 1, Wp = Ww >> 1;
        const size_t plane = (size_t)Hp * Wp;
        int hp = (h0 + gr * 2) >> 1;
        size_t ob = ((size_t)b * 32 + ch * 16) * plane + (size_t)hp * Wp + ((w0 + tx) >> 1);
#pragma unroll
        for (int j = 0; j < 8; ++j) {
            float l0, u0, l1, u1;
            unpk(acc[0][j], l0, u0);
            unpk(acc[1][j], l1, u1);
            float m0 = fmaxf(l0, l1), m1 = fmaxf(u0, u1);
            m0 = fmaxf(m0, __shfl_xor_sync(0xffffffffu, m0, 1));
            m1 = fmaxf(m1, __shfl_xor_sync(0xffffffffu, m1, 1));
            if (!(tx & 1)) {
                out[ob + (size_t)(2 * j) * plane] = m0;
                out[ob + (size_t)(2 * j + 1) * plane] = m1;
            }
        }
    } else {
        const size_t plane = (size_t)Hh * Ww;
#pragma unroll
        for (int p = 0; p < 2; ++p) {
            int h = h0 + gr * 2 + p;
            size_t ob = ((size_t)b * 32 + ch * 16) * plane + (size_t)h * Ww + (w0 + tx);
#pragma unroll
            for (int j = 0; j < 8; ++j) {
                float lo, hi;
                unpk(acc[p][j], lo, hi);
                out[ob + (size_t)(2 * j) * plane] = lo;
                out[ob + (size_t)(2 * j + 1) * plane] = hi;
            }
        }
    }
}

// ---------------- composed deconv+conv interior ----------------
template <int MODE>
__global__ void __launch_bounds__(256, 3)
dconv_kernel(const float* __restrict__ in, const float* __restrict__ ck,
             const float* __restrict__ cbias, float* __restrict__ out,
             int Hi, int Wi, const float* __restrict__ orig) {
    __shared__ __align__(16) float s_in[2][640];
    __shared__ __align__(16) float s_w[2][2048];
    const int tx = threadIdx.x, ty = threadIdx.y, tid = ty * 32 + tx;
    const int c0 = blockIdx.x * 32, a0 = blockIdx.y * 2;
    const int b = blockIdx.z;

    auto issue = [&](int ci0, int buf) {
        const float* kw = ck + (size_t)ci0 * 512;
#pragma unroll
        for (int k = 0; k < 3; ++k) {
            int i = tid + k * 256;
            if (i < 160) {
                int cc = i / 40, rem = i - cc * 40;
                int r = rem / 10, pi = rem - r * 10;
                int gh = a0 - 1 + r;
                int gw0 = c0 - 4 + pi * 4;
                bool ok = (gh >= 0 && gh < Hi && gw0 >= 0 && gw0 + 4 <= Wi);
                const float* g = ok ? &in[(((size_t)b * 32 + ci0 + cc) * Hi + gh) * Wi + gw0] : in;
                cpa16(scvt(&s_in[buf][cc * 160 + r * 40 + pi * 4]), g, ok);
            } else if (i < 672) {
                int j = i - 160;
                cpa16f(scvt(&s_w[buf][j * 4]), kw + j * 4);
            }
        }
    };
    issue(0, 0);
    CP_COMMIT();

    u64 acc[4][2][2];
#pragma unroll
    for (int pr = 0; pr < 2; ++pr) {
        u64 bv = pk2(cbias[ty * 4 + 2 * pr], cbias[ty * 4 + 2 * pr + 1]);
#pragma unroll
        for (int r = 0; r < 4; ++r) { acc[r][0][pr] = bv; acc[r][1][pr] = bv; }
    }

    int buf = 0;
    for (int ci0 = 0; ci0 < 32; ci0 += 4) {
        CP_WAIT0();
        __syncthreads();
        if (ci0 + 4 < 32) { issue(ci0 + 4, buf ^ 1); CP_COMMIT(); }
#pragma unroll
        for (int cc = 0; cc < 4; ++cc) {
            const float* ib = &s_in[buf][cc * 160 + tx + 3];
            u64 vpk[4][3];
#pragma unroll
            for (int r4 = 0; r4 < 4; ++r4)
#pragma unroll
                for (int dc = 0; dc < 3; ++dc)
                    vpk[r4][dc] = pk(ib[r4 * 40 + dc]);
            const float* wb = &s_w[buf][cc * 512];
#pragma unroll
            for (int ph = 0; ph < 2; ++ph)
#pragma unroll
                for (int pw = 0; pw < 2; ++pw)
#pragma unroll
                    for (int r = 0; r < 2; ++r)
#pragma unroll
                        for (int c = 0; c < 2; ++c) {
                            const u64* wq = (const u64*)(wb + ((ph * 2 + pw) * 4 + r * 2 + c) * 32) + ty * 2;
                            u64 q0 = wq[0], q1 = wq[1];
#pragma unroll
                            for (int half = 0; half < 2; ++half) {
                                u64 v = vpk[half + ph + r][pw + c];
                                fma2(acc[half * 2 + ph][pw][0], v, q0);
                                fma2(acc[half * 2 + ph][pw][1], v, q1);
                            }
                        }
        }
        buf ^= 1;
    }

    const int Ho = 2 * Hi, Wo = 2 * Wi;
    const size_t plane = (size_t)Ho * Wo;
    const int wq0 = 2 * (c0 + tx);
#pragma unroll
    for (int row = 0; row < 4; ++row) {
        int h = 2 * a0 + row;
        if (h < 1 || h >= Ho - 1) continue;
#pragma unroll
        for (int pr = 0; pr < 2; ++pr) {
            float p0l, p0h, p1l, p1h;
            unpk(acc[row][0][pr], p0l, p0h);
            unpk(acc[row][1][pr], p1l, p1h);
            size_t ob = ((size_t)(b * 32 + ty * 4 + 2 * pr)) * plane + (size_t)h * Wo + wq0;
            if (wq0 == 0) {
                float v0 = p1l, v1 = p1h;
                if (MODE == 2) { v0 *= orig[ob + 1]; v1 *= orig[ob + plane + 1]; }
                out[ob + 1] = v0;
                out[ob + plane + 1] = v1;
            } else if (wq0 == Wo - 2) {
                float v0 = p0l, v1 = p0h;
                if (MODE == 2) { v0 *= orig[ob]; v1 *= orig[ob + plane]; }
                out[ob] = v0;
                out[ob + plane] = v1;
            } else {
                float2 f0 = make_float2(p0l, p1l);
                float2 f1 = make_float2(p0h, p1h);
                if (MODE == 2) {
                    float2 g0 = *(const float2*)(orig + ob);
                    float2 g1 = *(const float2*)(orig + ob + plane);
                    f0.x *= g0.x; f0.y *= g0.y;
                    f1.x *= g1.x; f1.y *= g1.y;
                }
                *(float2*)(out + ob) = f0;
                *(float2*)(out + ob + plane) = f1;
            }
        }
    }
}

// ---------------- composed stage border: 1-px output frame ----------------
template <int MODE>
__global__ void __launch_bounds__(256, 2)
bconv_kernel(const float* __restrict__ in, const float* __restrict__ dw,
             const float* __restrict__ db, const float* __restrict__ cw,
             const float* __restrict__ cb, float* __restrict__ out,
             int Hi, int Wi, const float* __restrict__ orig) {
    __shared__ float s_dw[4096];
    __shared__ float s_cw[9216];
    __shared__ float s_db[32];
    const int tid = threadIdx.x;
    const int b = blockIdx.y;
    const int Ho = 2 * Hi, Wo = 2 * Wi;
    const int npix = 2 * Wo + 2 * (Ho - 2);
    const int px = blockIdx.x * 64 + (tid >> 2);
    const int cg = tid & 3;

    for (int i = tid; i < 4096; i += 256) {
        int m = i >> 7, rem = i & 127;
        int pp = (rem >> 6) & 1, qq = (rem >> 5) & 1, ci = rem & 31;
        s_dw[i] = dw[(((size_t)ci * 32 + m) * 2 + pp) * 2 + qq];
    }
    for (int i = tid; i < 9216; i += 256) {
        int tap = i >> 10, rem = i & 1023;
        int m = rem >> 5, co = rem & 31;
        s_cw[i] = cw[((size_t)co * 32 + m) * 9 + tap];
    }
    if (tid < 32) s_db[tid] = db[tid];
    __syncthreads();

    if (px >= npix) return;
    int t = px;
    int h, w;
    if (t < Wo) { h = 0; w = t; }
    else if (t < 2 * Wo) { h = Ho - 1; w = t - Wo; }
    else { int t2 = t - 2 * Wo; h = 1 + (t2 >> 1); w = (t2 & 1) ? (Wo - 1) : 0; }

    float acc[8];
#pragma unroll
    for (int j = 0; j < 8; ++j) acc[j] = cb[cg * 8 + j];

    for (int di = 0; di < 3; ++di)
        for (int dj = 0; dj < 3; ++dj) {
            int p = h - 1 + di, q = w - 1 + dj;
            if (p < 0 || p >= Ho || q < 0 || q >= Wo) continue;
            int ip = p >> 1, pp = p & 1, iq = q >> 1, qq = q & 1;
            float inv[32];
#pragma unroll
            for (int ci = 0; ci < 32; ++ci)
                inv[ci] = in[((size_t)(b * 32 + ci) * Hi + ip) * Wi + iq];
            const float* dwb = &s_dw[(pp * 2 + qq) * 32];
            const float* cwt = &s_cw[(di * 3 + dj) * 1024 + cg * 8];
#pragma unroll 4
            for (int m = 0; m < 32; ++m) {
                float t1m = s_db[m];
#pragma unroll
                for (int ci = 0; ci < 32; ++ci) t1m += inv[ci] * dwb[m * 128 + ci];
                const float* cwm = cwt + m * 32;
#pragma unroll
                for (int j = 0; j < 8; ++j) acc[j] += t1m * cwm[j];
            }
        }

    {
        const size_t plane = (size_t)Ho * Wo;
        size_t ob = ((size_t)(b * 32 + cg * 8)) * plane + (size_t)h * Wo + w;
#pragma unroll
        for (int j = 0; j < 8; ++j) {
            float v = acc[j];
            if (MODE == 2) v *= orig[ob + (size_t)j * plane];
            out[ob + (size_t)j * plane] = v;
        }
    }
}

// ---------------- host launch ----------------
extern "C" void kernel_launch(void* const* d_in, const int* in_sizes, int n_in,
                              void* d_out, int out_size) {
    const float* x = (const float*)d_in[0];
    const float* w1 = (const float*)d_in[1];   const float* b1 = (const float*)d_in[2];
    const float* w2 = (const float*)d_in[3];   const float* b2 = (const float*)d_in[4];
    const float* w3 = (const float*)d_in[5];   const float* b3 = (const float*)d_in[6];
    const float* w4 = (const float*)d_in[7];   const float* b4 = (const float*)d_in[8];
    const float* w5 = (const float*)d_in[9];   const float* b5 = (const float*)d_in[10];
    const float* w6 = (const float*)d_in[11];  const float* b6 = (const float*)d_in[12];
    const float* w7 = (const float*)d_in[13];  const float* b7 = (const float*)d_in[14];
    const float* dw1 = (const float*)d_in[15]; const float* db1 = (const float*)d_in[16];
    const float* dw2 = (const float*)d_in[17]; const float* db2 = (const float*)d_in[18];
    const float* dw3 = (const float*)d_in[19]; const float* db3 = (const float*)d_in[20];
    float* outp = (float*)d_out;

    void* p;
    cudaGetSymbolAddress(&p, g_s1);   float* s1 = (float*)p;
    cudaGetSymbolAddress(&p, g_s2);   float* s2 = (float*)p;
    cudaGetSymbolAddress(&p, g_q1);   float* q1 = (float*)p;
    cudaGetSymbolAddress(&p, g_q2);   float* q2 = (float*)p;
    cudaGetSymbolAddress(&p, g_e1);   float* e1 = (float*)p;
    cudaGetSymbolAddress(&p, g_e2);   float* e2 = (float*)p;
    cudaGetSymbolAddress(&p, g_w3x3); float* wt = (float*)p;
    cudaGetSymbolAddress(&p, g_ck);   float* ckp = (float*)p;
    cudaGetSymbolAddress(&p, g_cb);   float* cbp = (float*)p;

    dim3 blk(32, 8);

    // stats + keff first so conv1_5x5 stays the 4th launch (ncu capture slot)
    stats_op_kernel<<<dim3(16, 16, B_ * C_), blk>>>(x);
    stats2_kernel<<<21, 256>>>(w1);
    keff_kernel<<<dim3(B_, 33), 32>>>(w1, b1);
    conv1_5x5_kernel<<<dim3(16, 64, B_), blk>>>(x, s1);
    conv1_strip_kernel<<<dim3(64, B_), blk>>>(x, w1, b1, s1);

    // remaining weight prep
    prep_w_kernel<<<3, 256>>>(w2, w3, w4);
    ck_kernel<<<dim3(33, 3), 32>>>(dw1, db1, w5, b5, dw2, db2, w6, b6, dw3, db3, w7, b7);

    // conv2 + pool: s1 -> q1 (128^2)
    conv3x3_kernel<1><<<dim3(8, 32, B_), blk>>>(s1, wt + 0 * 9216, b2, q1, 256, 256);
    // conv3 + pool: q1 -> e1 (64^2)
    conv3x3_kernel<1><<<dim3(4, 16, B_), blk>>>(q1, wt + 1 * 9216, b3, e1, 128, 128);
    // conv4: e1 -> e2 (64^2)
    conv3x3_kernel<0><<<dim3(2, 8, B_), blk>>>(e1, wt + 2 * 9216, b4, e2, 64, 64);

    // stage1: composed deconv1+conv5: e2 (64^2) -> q2 (128^2)
    bconv_kernel<0><<<dim3(8, B_), 256>>>(e2, dw1, db1, w5, b5, q2, 64, 64, nullptr);
    dconv_kernel<0><<<dim3(2, 32, B_), blk>>>(e2, ckp + 0 * 16384, cbp + 0, q2, 64, 64, nullptr);
    // stage2: composed deconv2+conv6: q2 (128^2) -> s2 (256^2)
    bconv_kernel<0><<<dim3(16, B_), 256>>>(q2, dw2, db2, w6, b6, s2, 128, 128, nullptr);
    dconv_kernel<0><<<dim3(4, 64, B_), blk>>>(q2, ckp + 1 * 16384, cbp + 32, s2, 128, 128, nullptr);
    // stage3: composed deconv3+conv7 (+ orig mult): s2 (256^2) -> out (512^2)
    bconv_kernel<2><<<dim3(32, B_), 256>>>(s2, dw3, db3, w7, b7, outp, 256, 256, x);
    dconv_kernel<2><<<dim3(8, 128, B_), blk>>>(s2, ckp + 2 * 16384, cbp + 64, outp, 256, 256, x);
}

// round 15
// speedup vs baseline: 1.0504x; 1.0504x over previous
#include <cuda_runtime.h>

#define B_ 4
#define C_ 32
#define H_ 512
#define W_ 512

// ---------------- scratch (device globals; no runtime allocation) ----------------
static __device__ float g_s1[(size_t)B_ * C_ * 256 * 256];
static __device__ float g_s2[(size_t)B_ * C_ * 256 * 256];
static __device__ float g_q1[(size_t)B_ * C_ * 128 * 128];
static __device__ float g_q2[(size_t)B_ * C_ * 128 * 128];
static __device__ float g_e1[(size_t)B_ * C_ * 64 * 64];
static __device__ float g_e2[(size_t)B_ * C_ * 64 * 64];
static __device__ float g_partS[20 * 8192];
static __device__ float g_partQ[20 * 8192];
static __device__ float g_norm[40];                         // (mean, inv_std) per (b, branch)
static __device__ float g_keff[(size_t)B_ * 32 * 25 * 32];  // composed 5x5 kernels [b][ci][tap][co]
static __device__ float g_c1[B_ * 32];                      // conv1 constant term
static __device__ float g_ws[160];                          // sum of w1 over (ci,taps): [co][br]
static __device__ float g_w3x3[3 * 9216];                   // transposed [ci][tap][co] for w2..w4
static __device__ float g_ck[3 * 16384];                    // composed deconv+conv: [st][ci][phw][cell][co]
static __device__ float g_cb[96];                           // composed bias per stage [st][co]

// ---------------- packed f32x2 helpers ----------------
typedef unsigned long long u64;

__device__ __forceinline__ u64 pk(float v) {
    u64 r; asm("mov.b64 %0, {%1, %1};" : "=l"(r) : "f"(v)); return r;
}
__device__ __forceinline__ u64 pk2(float a, float b) {
    u64 r; asm("mov.b64 %0, {%1, %2};" : "=l"(r) : "f"(a), "f"(b)); return r;
}
__device__ __forceinline__ void fma2(u64& d, u64 a, u64 b) {
    asm("fma.rn.f32x2 %0, %1, %2, %0;" : "+l"(d) : "l"(a), "l"(b));
}
__device__ __forceinline__ void unpk(u64 v, float& lo, float& hi) {
    asm("mov.b64 {%0, %1}, %2;" : "=f"(lo), "=f"(hi) : "l"(v));
}

// ---------------- cp.async helpers ----------------
__device__ __forceinline__ unsigned scvt(const void* p) {
    return (unsigned)__cvta_generic_to_shared(p);
}
__device__ __forceinline__ void cpa4f(unsigned s, const float* g) {
    asm volatile("cp.async.ca.shared.global [%0], [%1], 4;" :: "r"(s), "l"(g));
}
__device__ __forceinline__ void cpa16(unsigned s, const float* g, bool ok) {
    asm volatile("cp.async.cg.shared.global [%0], [%1], 16, %2;"
                 :: "r"(s), "l"(g), "r"(ok ? 16 : 0));
}
__device__ __forceinline__ void cpa16f(unsigned s, const float* g) {
    asm volatile("cp.async.cg.shared.global [%0], [%1], 16;" :: "r"(s), "l"(g));
}
#define CP_COMMIT() asm volatile("cp.async.commit_group;" ::: "memory")
#define CP_WAIT0()  asm volatile("cp.async.wait_group 0;" ::: "memory")

// ---------------- shared edge-operator math ----------------
__device__ __forceinline__ void edge5(float a00, float a01, float a02,
                                      float a10, float a11, float a12,
                                      float a20, float a21, float a22, float o[5]) {
    float sxv = -a00 + a02 - 2.f * a10 + 2.f * a12 - a20 + a22;
    float syv = -a00 - 2.f * a01 - a02 + a20 + 2.f * a21 + a22;
    o[0] = 0.5f * (sxv + syv);
    float cxv = -3.f * a00 + 3.f * a02 - 10.f * a10 + 10.f * a12 - 3.f * a20 + 3.f * a22;
    float cyv = -3.f * a00 - 10.f * a01 - 3.f * a02 + 3.f * a20 + 10.f * a21 + 3.f * a22;
    o[1] = 0.5f * (cxv + cyv);
    o[2] = 2.f * a00 + 2.f * a02 - 8.f * a11 + 2.f * a20 + 2.f * a22;
    o[3] = 0.5f * ((-a00 + a11) + (-a01 + a10));
    float pxv = a00 + a01 + a02 - a20 - a21 - a22;
    float pyv = -a00 + a02 - a10 + a12 - a20 + a22;
    o[4] = 0.5f * (pxv + pyv);
}

static __device__ const float G_[5][3][3] = {
    {{-1.f, -1.f, 0.f}, {-1.f, 0.f, 1.f}, {0.f, 1.f, 1.f}},
    {{-3.f, -5.f, 0.f}, {-5.f, 0.f, 5.f}, {0.f, 5.f, 3.f}},
    {{2.f, 0.f, 2.f}, {0.f, -8.f, 0.f}, {2.f, 0.f, 2.f}},
    {{-0.5f, -0.5f, 0.f}, {0.5f, 0.5f, 0.f}, {0.f, 0.f, 0.f}},
    {{0.f, 0.5f, 1.f}, {-0.5f, 0.f, 0.5f}, {-1.f, -0.5f, 0.f}}
};

__device__ __forceinline__ int refl(int i, int n) {
    return i < 0 ? -i : (i >= n ? 2 * n - 2 - i : i);
}

// ---------------- fused operator + partial stats (4 px/thread) ----------------
__global__ void stats_op_kernel(const float* __restrict__ x) {
    __shared__ float sx[34 * 34];
    __shared__ float red[8][10];
    const int tx = threadIdx.x, ty = threadIdx.y;
    const int tid = ty * 32 + tx;
    const int w0 = blockIdx.x * 32, h0 = blockIdx.y * 32;
    const int bc = blockIdx.z;
    const int b = bc >> 5, c = bc & 31;
    const float* xp = x + (size_t)bc * H_ * W_;

    for (int i = tid; i < 1156; i += 256) {
        int r = i / 34, cl = i - r * 34;
        sx[i] = xp[refl(h0 - 1 + r, H_) * W_ + refl(w0 - 1 + cl, W_)];
    }
    __syncthreads();

    float s[5] = {0.f, 0.f, 0.f, 0.f, 0.f}, q[5] = {0.f, 0.f, 0.f, 0.f, 0.f};
#pragma unroll
    for (int k = 0; k < 4; ++k) {
        const int r = ty * 4 + k;
        float o[5];
        edge5(sx[r * 34 + tx], sx[r * 34 + tx + 1], sx[r * 34 + tx + 2],
              sx[(r + 1) * 34 + tx], sx[(r + 1) * 34 + tx + 1], sx[(r + 1) * 34 + tx + 2],
              sx[(r + 2) * 34 + tx], sx[(r + 2) * 34 + tx + 1], sx[(r + 2) * 34 + tx + 2], o);
#pragma unroll
        for (int br = 0; br < 5; ++br) {
            s[br] += o[br];
            q[br] += o[br] * o[br];
        }
    }

#pragma unroll
    for (int br = 0; br < 5; ++br) {
        float sv = s[br], qv = q[br];
#pragma unroll
        for (int off = 16; off; off >>= 1) {
            sv += __shfl_down_sync(0xffffffffu, sv, off);
            qv += __shfl_down_sync(0xffffffffu, qv, off);
        }
        if (tx == 0) { red[ty][br] = sv; red[ty][5 + br] = qv; }
    }
    __syncthreads();
    if (tid < 10) {
        float t = 0.f;
#pragma unroll
        for (int w = 0; w < 8; ++w) t += red[w][tid];
        int tile = blockIdx.x + 16 * blockIdx.y + 256 * c;
        if (tid < 5) g_partS[(b * 5 + tid) * 8192 + tile] = t;
        else         g_partQ[(b * 5 + tid - 5) * 8192 + tile] = t;
    }
}

// stage2 (blocks 0-19) + w1 sums (block 20)
__global__ void stats2_kernel(const float* __restrict__ w1) {
    if (blockIdx.x == 20) {
        int t = threadIdx.x;
        if (t < 160) {
            int co = t / 5, br = t % 5;
            float s = 0.f;
            for (int ci = 0; ci < 32; ++ci) {
                const float* wq = &w1[((size_t)co * 160 + br * 32 + ci) * 9];
#pragma unroll
                for (int u = 0; u < 9; ++u) s += wq[u];
            }
            g_ws[t] = s;
        }
        return;
    }
    __shared__ float rs[256], rq[256];
    const int seg = blockIdx.x, t = threadIdx.x;
    float s = 0.f, q = 0.f;
    for (int i = t; i < 8192; i += 256) {
        s += g_partS[seg * 8192 + i];
        q += g_partQ[seg * 8192 + i];
    }
    rs[t] = s; rq[t] = q;
    __syncthreads();
    for (int st = 128; st > 0; st >>= 1) {
        if (t < st) { rs[t] += rs[t + st]; rq[t] += rq[t + st]; }
        __syncthreads();
    }
    if (t == 0) {
        const double N = (double)32 * H_ * W_;
        double mean = (double)rs[0] / N;
        double var = (double)rq[0] / N - mean * mean;
        if (var < 1e-30) var = 1e-30;
        g_norm[seg * 2 + 0] = (float)mean;
        g_norm[seg * 2 + 1] = (float)(1.0 / sqrt(var));
    }
}

// ---------------- weight prep: transpose w2..w4 ----------------
__global__ void prep_w_kernel(const float* w2, const float* w3, const float* w4) {
    const float* src[3] = {w2, w3, w4};
    const float* s = src[blockIdx.x];
    float* dst = g_w3x3 + blockIdx.x * 9216;
    for (int i = threadIdx.x; i < 9216; i += 256) {
        int ci = i / 288, rem = i - ci * 288;
        int tap = rem >> 5, co = rem & 31;
        dst[i] = s[((size_t)co * 32 + ci) * 9 + tap];
    }
}

// keff (ci < 32) + c1 constant (ci == 32)
__global__ void keff_kernel(const float* __restrict__ w1, const float* __restrict__ b1) {
    const int b = blockIdx.x, ci = blockIdx.y, co = threadIdx.x;
    if (ci == 32) {
        float s = b1[co];
#pragma unroll
        for (int br = 0; br < 5; ++br) {
            float m = g_norm[(b * 5 + br) * 2], ns = g_norm[(b * 5 + br) * 2 + 1];
            s -= m * ns * g_ws[co * 5 + br];
        }
        g_c1[b * 32 + co] = s;
        return;
    }
    float k[25];
#pragma unroll
    for (int t = 0; t < 25; ++t) k[t] = 0.f;
#pragma unroll
    for (int br = 0; br < 5; ++br) {
        float ns = g_norm[(b * 5 + br) * 2 + 1];
#pragma unroll
        for (int ui = 0; ui < 3; ++ui)
#pragma unroll
            for (int uj = 0; uj < 3; ++uj) {
                float wv = ns * w1[(((size_t)co * 160 + br * 32 + ci) * 3 + ui) * 3 + uj];
#pragma unroll
                for (int vi = 0; vi < 3; ++vi)
#pragma unroll
                    for (int vj = 0; vj < 3; ++vj)
                        k[(ui + vi) * 5 + (uj + vj)] += wv * G_[br][vi][vj];
            }
    }
    for (int t = 0; t < 25; ++t)
        g_keff[(((size_t)b * 32 + ci) * 25 + t) * 32 + co] = k[t];
}

// ---------------- composed deconv2x2(s2)+conv3x3 weights ----------------
__global__ void ck_kernel(const float* dw1, const float* db1, const float* w5, const float* b5,
                          const float* dw2, const float* db2, const float* w6, const float* b6,
                          const float* dw3, const float* db3, const float* w7, const float* b7) {
    const int st = blockIdx.y;
    const float* dw = st == 0 ? dw1 : st == 1 ? dw2 : dw3;
    const float* db = st == 0 ? db1 : st == 1 ? db2 : db3;
    const float* cw = st == 0 ? w5 : st == 1 ? w6 : w7;
    const float* cb = st == 0 ? b5 : st == 1 ? b6 : b7;
    const int ci = blockIdx.x, co = threadIdx.x;
    if (ci == 32) {
        float s = cb[co];
        for (int m = 0; m < 32; ++m) {
            float ws = 0.f;
#pragma unroll
            for (int t = 0; t < 9; ++t) ws += cw[((size_t)co * 32 + m) * 9 + t];
            s += db[m] * ws;
        }
        g_cb[st * 32 + co] = s;
        return;
    }
    float K[4][4];
#pragma unroll
    for (int i = 0; i < 4; ++i)
#pragma unroll
        for (int j = 0; j < 4; ++j) K[i][j] = 0.f;
    for (int m = 0; m < 32; ++m) {
        float dv[2][2];
#pragma unroll
        for (int pp = 0; pp < 2; ++pp)
#pragma unroll
            for (int qq = 0; qq < 2; ++qq)
                dv[pp][qq] = dw[(((size_t)ci * 32 + m) * 2 + pp) * 2 + qq];
        const float* cwm = &cw[((size_t)co * 32 + m) * 9];
#pragma unroll
        for (int ph = 0; ph < 2; ++ph)
#pragma unroll
            for (int pw = 0; pw < 2; ++pw)
#pragma unroll
                for (int di = 0; di < 3; ++di) {
                    int sh = di + 1 - ph, r = sh >> 1, pp = sh & 1;
#pragma unroll
                    for (int dj = 0; dj < 3; ++dj) {
                        int sw = dj + 1 - pw, c = sw >> 1, qq = sw & 1;
                        K[ph * 2 + pw][r * 2 + c] += dv[pp][qq] * cwm[di * 3 + dj];
                    }
                }
    }
#pragma unroll
    for (int phw = 0; phw < 4; ++phw)
#pragma unroll
        for (int cell = 0; cell < 4; ++cell)
            g_ck[st * 16384 + ((ci * 4 + phw) * 4 + cell) * 32 + co] = K[phw][cell];
}

// ---------------- conv1 interior: composed 5x5 conv + thread-local 2x2 pool -----------
// tile 64w x 8h; thread = 2x2 pixels x 16 co. grid (8, 64, B), block (32,8)
__global__ void __launch_bounds__(256, 2)
conv1_5x5_kernel(const float* __restrict__ x, float* __restrict__ out) {
    constexpr int RW = 72;             // padded row stride (floats)
    constexpr int CT = 12 * RW;        // per-ci tile = 864 floats
    __shared__ __align__(16) float s_x[2][4 * CT];
    __shared__ __align__(16) float s_w[2][3200];
    const int tx = threadIdx.x, ty = threadIdx.y, tid = ty * 32 + tx;
    const int w0 = 2 + blockIdx.x * 64, h0 = 2 + blockIdx.y * 8;
    const int b = blockIdx.z;
    const int gr = ty & 3, ch = ty >> 2;
    const bool fast = (blockIdx.x < 7) && (blockIdx.y < 63);

    auto issue = [&](int ci0, int buf) {
        const float* kw = g_keff + (size_t)(b * 32 + ci0) * 800;
        if (fast) {
            // 816 input packets (4cc x 12r x 17p) + 800 weight packets
#pragma unroll
            for (int k = 0; k < 7; ++k) {
                int i = tid + k * 256;
                if (i < 816) {
                    int cc = i / 204, rem = i - cc * 204;
                    int r = rem / 17, p = rem - r * 17;
                    cpa16f(scvt(&s_x[buf][cc * CT + r * RW + p * 4]),
                           &x[((size_t)(b * 32 + ci0 + cc) * 512 + (h0 - 2 + r)) * 512 + (w0 - 2) + p * 4]);
                } else if (i < 1616) {
                    int j = i - 816;
                    cpa16f(scvt(&s_w[buf][j * 4]), kw + j * 4);
                }
            }
        } else {
            // per-element reflected loads: 4cc x 12r x 68c = 3264
#pragma unroll
            for (int k = 0; k < 13; ++k) {
                int i = tid + k * 256;
                if (i < 3264) {
                    int cc = i / 816, rem = i - cc * 816;
                    int r = rem / 68, cl = rem - r * 68;
                    cpa4f(scvt(&s_x[buf][cc * CT + r * RW + cl]),
                          &x[((size_t)(b * 32 + ci0 + cc) * 512 + refl(h0 - 2 + r, 512)) * 512 + refl(w0 - 2 + cl, 512)]);
                }
            }
#pragma unroll
            for (int k = 0; k < 4; ++k) {
                int i = tid + k * 256;
                if (i < 800)
                    cpa16f(scvt(&s_w[buf][i * 4]), kw + i * 4);
            }
        }
    };
    issue(0, 0);
    CP_COMMIT();

    u64 acc[2][2][8];          // [row r][col c][co pair]
#pragma unroll
    for (int j = 0; j < 8; ++j) {
        u64 cv = pk2(g_c1[b * 32 + ch * 16 + 2 * j], g_c1[b * 32 + ch * 16 + 2 * j + 1]);
        acc[0][0][j] = cv; acc[0][1][j] = cv;
        acc[1][0][j] = cv; acc[1][1][j] = cv;
    }

    int buf = 0;
    for (int ci0 = 0; ci0 < 32; ci0 += 4) {
        CP_WAIT0();
        __syncthreads();
        if (ci0 + 4 < 32) { issue(ci0 + 4, buf ^ 1); CP_COMMIT(); }
#pragma unroll
        for (int cc = 0; cc < 4; ++cc) {
            const float* ib = &s_x[buf][cc * CT + (2 * gr) * RW + 2 * tx];
            const float* wb = &s_w[buf][cc * 800];
            float rowf[2][6];
            {
                const float2* rp = (const float2*)ib;
                float2 a0 = rp[0], a1 = rp[1], a2 = rp[2];
                rowf[0][0] = a0.x; rowf[0][1] = a0.y;
                rowf[0][2] = a1.x; rowf[0][3] = a1.y;
                rowf[0][4] = a2.x; rowf[0][5] = a2.y;
            }
#pragma unroll
            for (int ti = 0; ti < 5; ++ti) {
                {
                    const float2* rp = (const float2*)(ib + (ti + 1) * RW);
                    float2 a0 = rp[0], a1 = rp[1], a2 = rp[2];
                    float* nx = rowf[(ti + 1) & 1];
                    nx[0] = a0.x; nx[1] = a0.y;
                    nx[2] = a1.x; nx[3] = a1.y;
                    nx[4] = a2.x; nx[5] = a2.y;
                }
                const float* cur = rowf[ti & 1];
                const float* nxt = rowf[(ti + 1) & 1];
#pragma unroll
                for (int tj = 0; tj < 5; ++tj) {
                    u64 v00 = pk(cur[tj]);
                    u64 v01 = pk(cur[tj + 1]);
                    u64 v10 = pk(nxt[tj]);
                    u64 v11 = pk(nxt[tj + 1]);
                    const u64* wq = (const u64*)(wb + (ti * 5 + tj) * 32) + ch * 8;
#pragma unroll
                    for (int j = 0; j < 8; ++j) {
                        u64 q = wq[j];
                        fma2(acc[0][0][j], v00, q);
                        fma2(acc[0][1][j], v01, q);
                        fma2(acc[1][0][j], v10, q);
                        fma2(acc[1][1][j], v11, q);
                    }
                }
            }
        }
        buf ^= 1;
    }

    // thread-local 2x2 pool -> pooled cell (hp, wp)
    const int hp = (h0 >> 1) + gr;          // 1 + 4*by + gr
    const int wp = (w0 >> 1) + tx;          // 1 + 32*bx + tx
    const size_t plane = 65536;
    if (hp < 255 && wp < 255) {
        size_t ob = ((size_t)b * 32 + ch * 16) * plane + (size_t)hp * 256 + wp;
#pragma unroll
        for (int j = 0; j < 8; ++j) {
            float a, bb, c, d, e, f, g, h;
            unpk(acc[0][0][j], a, bb);
            unpk(acc[0][1][j], c, d);
            unpk(acc[1][0][j], e, f);
            unpk(acc[1][1][j], g, h);
            float m0 = fmaxf(fmaxf(a, c), fmaxf(e, g));
            float m1 = fmaxf(fmaxf(bb, d), fmaxf(f, h));
            out[ob + (size_t)(2 * j) * plane] = m0;
            out[ob + (size_t)(2 * j + 1) * plane] = m1;
        }
    }
}

// ---------------- conv1 border strips (2 conv rows/cols only) ----------------
__global__ void __launch_bounds__(256, 2)
conv1_strip_kernel(const float* __restrict__ x, const float* __restrict__ wgt,
                   const float* __restrict__ bias, float* __restrict__ out) {
    __shared__ __align__(16) float s_x[2][216];
    __shared__ __align__(16) float s_op[5][136];
    __shared__ __align__(16) float s_w[2][1440];
    __shared__ float s_nm[5], s_ns[5];
    const int tx = threadIdx.x, ty = threadIdx.y, tid = ty * 32 + tx;
    const int b = blockIdx.y;
    int si = blockIdx.x;
    const bool vert = si >= 32;
    si &= 31;
    const int longB = (si & 15) * 32;
    const int shortB = (si < 16) ? 0 : 510;

    if (tid < 5) {
        s_nm[tid] = g_norm[(b * 5 + tid) * 2 + 0];
        s_ns[tid] = g_norm[(b * 5 + tid) * 2 + 1];
    }

    if (tid < 216) {
        int r = tid / 36, c = tid - r * 36;
        int gh = vert ? (longB - 2 + c) : (shortB - 2 + r);
        int gw = vert ? (shortB - 2 + r) : (longB - 2 + c);
        s_x[0][tid] = x[((size_t)b * 32 * 512 + refl(gh, 512)) * 512 + refl(gw, 512)];
    }
#pragma unroll
    for (int k = 0; k < 6; ++k) {
        int i = tid + k * 256;
        if (i < 1440) {
            int br = i / 288, rem = i - br * 288;
            int tap = rem >> 5, co = rem & 31;
            s_w[0][i] = wgt[((size_t)co * 160 + br * 32) * 9 + tap];
        }
    }
    __syncthreads();

    u64 acc[2][2];
#pragma unroll
    for (int q = 0; q < 2; ++q) {
        u64 bv = pk2(bias[ty * 4 + 2 * q], bias[ty * 4 + 2 * q + 1]);
        acc[0][q] = bv; acc[1][q] = bv;
    }

    int buf = 0;
    for (int ci = 0; ci < 32; ++ci) {
        const bool more = (ci + 1 < 32);
        float rx, rw[6];
        if (more) {
            if (tid < 216) {
                int r = tid / 36, c = tid - r * 36;
                int gh = vert ? (longB - 2 + c) : (shortB - 2 + r);
                int gw = vert ? (shortB - 2 + r) : (longB - 2 + c);
                rx = x[(((size_t)b * 32 + ci + 1) * 512 + refl(gh, 512)) * 512 + refl(gw, 512)];
            }
#pragma unroll
            for (int k = 0; k < 6; ++k) {
                int i = tid + k * 256;
                if (i < 1440) {
                    int br = i / 288, rem = i - br * 288;
                    int tap = rem >> 5, co = rem & 31;
                    rw[k] = wgt[((size_t)co * 160 + br * 32 + ci + 1) * 9 + tap];
                }
            }
        }
        if (tid < 136) {
            int sp = tid / 34, lp = tid - sp * 34;
            int h = vert ? (longB - 1 + lp) : (shortB - 1 + sp);
            int w = vert ? (shortB - 1 + sp) : (longB - 1 + lp);
            float o[5] = {0.f, 0.f, 0.f, 0.f, 0.f};
            if (h >= 0 && h < 512 && w >= 0 && w < 512) {
                float a[3][3];
#pragma unroll
                for (int dh = 0; dh < 3; ++dh)
#pragma unroll
                    for (int dw = 0; dw < 3; ++dw) {
                        int r = vert ? (sp + dw) : (sp + dh);
                        int c = vert ? (lp + dh) : (lp + dw);
                        a[dh][dw] = s_x[buf][r * 36 + c];
                    }
                edge5(a[0][0], a[0][1], a[0][2], a[1][0], a[1][1], a[1][2],
                      a[2][0], a[2][1], a[2][2], o);
#pragma unroll
                for (int k = 0; k < 5; ++k) o[k] = (o[k] - s_nm[k]) * s_ns[k];
            }
#pragma unroll
            for (int k = 0; k < 5; ++k) s_op[k][tid] = o[k];
        }
        __syncthreads();

#pragma unroll
        for (int br = 0; br < 5; ++br) {
#pragma unroll
            for (int ds = 0; ds < 3; ++ds)
#pragma unroll
                for (int dl = 0; dl < 3; ++dl) {
                    int tap = vert ? (dl * 3 + ds) : (ds * 3 + dl);
                    const u64* wq = (const u64*)(&s_w[buf][br * 288 + tap * 32]) + ty * 2;
                    u64 q0 = wq[0], q1 = wq[1];
#pragma unroll
                    for (int s = 0; s < 2; ++s) {
                        u64 v = pk(s_op[br][(s + ds) * 34 + tx + dl]);
                        fma2(acc[s][0], v, q0);
                        fma2(acc[s][1], v, q1);
                    }
                }
        }
        if (more) {
            if (tid < 216) s_x[buf ^ 1][tid] = rx;
#pragma unroll
            for (int k = 0; k < 6; ++k) {
                int i = tid + k * 256;
                if (i < 1440) s_w[buf ^ 1][i] = rw[k];
            }
        }
        __syncthreads();
        buf ^= 1;
    }

    const size_t plane = 65536;
    const int hp = vert ? ((longB + tx) >> 1) : (shortB >> 1);
    const int wp = vert ? (shortB >> 1) : ((longB + tx) >> 1);
#pragma unroll
    for (int q = 0; q < 2; ++q) {
        float l0, u0, l1, u1;
        unpk(acc[0][q], l0, u0);
        unpk(acc[1][q], l1, u1);
        float m0 = fmaxf(l0, l1), m1 = fmaxf(u0, u1);
        m0 = fmaxf(m0, __shfl_xor_sync(0xffffffffu, m0, 1));
        m1 = fmaxf(m1, __shfl_xor_sync(0xffffffffu, m1, 1));
        if (!(tx & 1)) {
            int co = ty * 4 + 2 * q;
            out[((size_t)(b * 32 + co) * plane) + (size_t)hp * 256 + wp] = m0;
            out[((size_t)(b * 32 + co + 1) * plane) + (size_t)hp * 256 + wp] = m1;
        }
    }
}

// ---------------- conv3x3 CIN=32 (zero pad), 16B cp.async pipelined ----------------
// MODE 0: plain; 1: fused pool
template <int MODE>
__global__ void __launch_bounds__(256, 3)
conv3x3_kernel(const float* __restrict__ in, const float* __restrict__ wgt,
               const float* __restrict__ bias, float* __restrict__ out,
               int Hh, int Ww) {
    constexpr int ROWW = 40;
    constexpr int CH = 4 * 10 * ROWW;
    __shared__ __align__(16) float s_in[2][CH];
    __shared__ __align__(16) float s_w[9216];
    const int tx = threadIdx.x, ty = threadIdx.y, tid = ty * 32 + tx;
    const int w0 = blockIdx.x * 32, h0 = blockIdx.y * 8;
    const int b = blockIdx.z;
    const int gr = ty & 3, ch = ty >> 2;

    {
        const float* g = wgt + tid * 4;
        unsigned sdst = scvt(&s_w[tid * 4]);
#pragma unroll
        for (int k = 0; k < 9; ++k) cpa16f(sdst + k * 4096, g + k * 1024);
    }
    auto issue = [&](int ci0, int buf) {
#pragma unroll
        for (int k = 0; k < 2; ++k) {
            int i = tid + k * 256;
            if (i < 400) {
                int cc = i / 100, rem = i - cc * 100;
                int r = rem / 10, pi = rem - r * 10;
                int gh = h0 - 1 + r;
                int gw0 = w0 - 4 + pi * 4;
                bool ok = (gh >= 0 && gh < Hh && gw0 >= 0 && gw0 + 4 <= Ww);
                const float* g = ok ? &in[(((size_t)b * 32 + ci0 + cc) * Hh + gh) * Ww + gw0] : in;
                cpa16(scvt(&s_in[buf][cc * 400 + r * ROWW + pi * 4]), g, ok);
            }
        }
    };
    issue(0, 0);
    CP_COMMIT();

    u64 acc[2][8];
#pragma unroll
    for (int j = 0; j < 8; ++j) {
        u64 bv = pk2(bias[ch * 16 + 2 * j], bias[ch * 16 + 2 * j + 1]);
        acc[0][j] = bv; acc[1][j] = bv;
    }

    int buf = 0;
    for (int ci0 = 0; ci0 < 32; ci0 += 4) {
        CP_WAIT0();
        __syncthreads();
        if (ci0 + 4 < 32) { issue(ci0 + 4, buf ^ 1); CP_COMMIT(); }
#pragma unroll
        for (int cc = 0; cc < 4; ++cc) {
            const float* ib = &s_in[buf][cc * 400 + (gr * 2) * ROWW + tx + 3];
            const float* wb = &s_w[(ci0 + cc) * 288];
#pragma unroll
            for (int di = 0; di < 3; ++di)
#pragma unroll
                for (int dj = 0; dj < 3; ++dj) {
                    u64 v0 = pk(ib[di * ROWW + dj]);
                    u64 v1 = pk(ib[(di + 1) * ROWW + dj]);
                    const u64* wq = (const u64*)(wb + (di * 3 + dj) * 32) + ch * 8;
                    u64 q0 = wq[0], q1 = wq[1], q2 = wq[2], q3 = wq[3];
                    u64 q4 = wq[4], q5 = wq[5], q6 = wq[6], q7 = wq[7];
                    fma2(acc[0][0], v0, q0); fma2(acc[0][1], v0, q1);
                    fma2(acc[0][2], v0, q2); fma2(acc[0][3], v0, q3);
                    fma2(acc[0][4], v0, q4); fma2(acc[0][5], v0, q5);
                    fma2(acc[0][6], v0, q6); fma2(acc[0][7], v0, q7);
                    fma2(acc[1][0], v1, q0); fma2(acc[1][1], v1, q1);
                    fma2(acc[1][2], v1, q2); fma2(acc[1][3], v1, q3);
                    fma2(acc[1][4], v1, q4); fma2(acc[1][5], v1, q5);
                    fma2(acc[1][6], v1, q6); fma2(acc[1][7], v1, q7);
                }
        }
        buf ^= 1;
    }

    if (MODE == 1) {
        const int Hp = Hh >> 1, Wp = Ww >> 1;
        const size_t plane = (size_t)Hp * Wp;
        int hp = (h0 + gr * 2) >> 1;
        size_t ob = ((size_t)b * 32 + ch * 16) * plane + (size_t)hp * Wp + ((w0 + tx) >> 1);
#pragma unroll
        for (int j = 0; j < 8; ++j) {
            float l0, u0, l1, u1;
            unpk(acc[0][j], l0, u0);
            unpk(acc[1][j], l1, u1);
            float m0 = fmaxf(l0, l1), m1 = fmaxf(u0, u1);
            m0 = fmaxf(m0, __shfl_xor_sync(0xffffffffu, m0, 1));
            m1 = fmaxf(m1, __shfl_xor_sync(0xffffffffu, m1, 1));
            if (!(tx & 1)) {
                out[ob + (size_t)(2 * j) * plane] = m0;
                out[ob + (size_t)(2 * j + 1) * plane] = m1;
            }
        }
    } else {
        const size_t plane = (size_t)Hh * Ww;
#pragma unroll
        for (int p = 0; p < 2; ++p) {
            int h = h0 + gr * 2 + p;
            size_t ob = ((size_t)b * 32 + ch * 16) * plane + (size_t)h * Ww + (w0 + tx);
#pragma unroll
            for (int j = 0; j < 8; ++j) {
                float lo, hi;
                unpk(acc[p][j], lo, hi);
                out[ob + (size_t)(2 * j) * plane] = lo;
                out[ob + (size_t)(2 * j + 1) * plane] = hi;
            }
        }
    }
}

// ---------------- composed deconv+conv interior ----------------
template <int MODE>
__global__ void __launch_bounds__(256, 3)
dconv_kernel(const float* __restrict__ in, const float* __restrict__ ck,
             const float* __restrict__ cbias, float* __restrict__ out,
             int Hi, int Wi, const float* __restrict__ orig) {
    __shared__ __align__(16) float s_in[2][640];
    __shared__ __align__(16) float s_w[2][2048];
    const int tx = threadIdx.x, ty = threadIdx.y, tid = ty * 32 + tx;
    const int c0 = blockIdx.x * 32, a0 = blockIdx.y * 2;
    const int b = blockIdx.z;

    auto issue = [&](int ci0, int buf) {
        const float* kw = ck + (size_t)ci0 * 512;
#pragma unroll
        for (int k = 0; k < 3; ++k) {
            int i = tid + k * 256;
            if (i < 160) {
                int cc = i / 40, rem = i - cc * 40;
                int r = rem / 10, pi = rem - r * 10;
                int gh = a0 - 1 + r;
                int gw0 = c0 - 4 + pi * 4;
                bool ok = (gh >= 0 && gh < Hi && gw0 >= 0 && gw0 + 4 <= Wi);
                const float* g = ok ? &in[(((size_t)b * 32 + ci0 + cc) * Hi + gh) * Wi + gw0] : in;
                cpa16(scvt(&s_in[buf][cc * 160 + r * 40 + pi * 4]), g, ok);
            } else if (i < 672) {
                int j = i - 160;
                cpa16f(scvt(&s_w[buf][j * 4]), kw + j * 4);
            }
        }
    };
    issue(0, 0);
    CP_COMMIT();

    u64 acc[4][2][2];
#pragma unroll
    for (int pr = 0; pr < 2; ++pr) {
        u64 bv = pk2(cbias[ty * 4 + 2 * pr], cbias[ty * 4 + 2 * pr + 1]);
#pragma unroll
        for (int r = 0; r < 4; ++r) { acc[r][0][pr] = bv; acc[r][1][pr] = bv; }
    }

    int buf = 0;
    for (int ci0 = 0; ci0 < 32; ci0 += 4) {
        CP_WAIT0();
        __syncthreads();
        if (ci0 + 4 < 32) { issue(ci0 + 4, buf ^ 1); CP_COMMIT(); }
#pragma unroll
        for (int cc = 0; cc < 4; ++cc) {
            const float* ib = &s_in[buf][cc * 160 + tx + 3];
            u64 vpk[4][3];
#pragma unroll
            for (int r4 = 0; r4 < 4; ++r4)
#pragma unroll
                for (int dc = 0; dc < 3; ++dc)
                    vpk[r4][dc] = pk(ib[r4 * 40 + dc]);
            const float* wb = &s_w[buf][cc * 512];
#pragma unroll
            for (int ph = 0; ph < 2; ++ph)
#pragma unroll
                for (int pw = 0; pw < 2; ++pw)
#pragma unroll
                    for (int r = 0; r < 2; ++r)
#pragma unroll
                        for (int c = 0; c < 2; ++c) {
                            const u64* wq = (const u64*)(wb + ((ph * 2 + pw) * 4 + r * 2 + c) * 32) + ty * 2;
                            u64 q0 = wq[0], q1 = wq[1];
#pragma unroll
                            for (int half = 0; half < 2; ++half) {
                                u64 v = vpk[half + ph + r][pw + c];
                                fma2(acc[half * 2 + ph][pw][0], v, q0);
                                fma2(acc[half * 2 + ph][pw][1], v, q1);
                            }
                        }
        }
        buf ^= 1;
    }

    const int Ho = 2 * Hi, Wo = 2 * Wi;
    const size_t plane = (size_t)Ho * Wo;
    const int wq0 = 2 * (c0 + tx);
#pragma unroll
    for (int row = 0; row < 4; ++row) {
        int h = 2 * a0 + row;
        if (h < 1 || h >= Ho - 1) continue;
#pragma unroll
        for (int pr = 0; pr < 2; ++pr) {
            float p0l, p0h, p1l, p1h;
            unpk(acc[row][0][pr], p0l, p0h);
            unpk(acc[row][1][pr], p1l, p1h);
            size_t ob = ((size_t)(b * 32 + ty * 4 + 2 * pr)) * plane + (size_t)h * Wo + wq0;
            if (wq0 == 0) {
                float v0 = p1l, v1 = p1h;
                if (MODE == 2) { v0 *= orig[ob + 1]; v1 *= orig[ob + plane + 1]; }
                out[ob + 1] = v0;
                out[ob + plane + 1] = v1;
            } else if (wq0 == Wo - 2) {
                float v0 = p0l, v1 = p0h;
                if (MODE == 2) { v0 *= orig[ob]; v1 *= orig[ob + plane]; }
                out[ob] = v0;
                out[ob + plane] = v1;
            } else {
                float2 f0 = make_float2(p0l, p1l);
                float2 f1 = make_float2(p0h, p1h);
                if (MODE == 2) {
                    float2 g0 = *(const float2*)(orig + ob);
                    float2 g1 = *(const float2*)(orig + ob + plane);
                    f0.x *= g0.x; f0.y *= g0.y;
                    f1.x *= g1.x; f1.y *= g1.y;
                }
                *(float2*)(out + ob) = f0;
                *(float2*)(out + ob + plane) = f1;
            }
        }
    }
}

// ---------------- composed stage border: 1-px output frame ----------------
template <int MODE>
__global__ void __launch_bounds__(256, 2)
bconv_kernel(const float* __restrict__ in, const float* __restrict__ dw,
             const float* __restrict__ db, const float* __restrict__ cw,
             const float* __restrict__ cb, float* __restrict__ out,
             int Hi, int Wi, const float* __restrict__ orig) {
    __shared__ float s_dw[4096];
    __shared__ float s_cw[9216];
    __shared__ float s_db[32];
    const int tid = threadIdx.x;
    const int b = blockIdx.y;
    const int Ho = 2 * Hi, Wo = 2 * Wi;
    const int npix = 2 * Wo + 2 * (Ho - 2);
    const int px = blockIdx.x * 64 + (tid >> 2);
    const int cg = tid & 3;

    for (int i = tid; i < 4096; i += 256) {
        int m = i >> 7, rem = i & 127;
        int pp = (rem >> 6) & 1, qq = (rem >> 5) & 1, ci = rem & 31;
        s_dw[i] = dw[(((size_t)ci * 32 + m) * 2 + pp) * 2 + qq];
    }
    for (int i = tid; i < 9216; i += 256) {
        int tap = i >> 10, rem = i & 1023;
        int m = rem >> 5, co = rem & 31;
        s_cw[i] = cw[((size_t)co * 32 + m) * 9 + tap];
    }
    if (tid < 32) s_db[tid] = db[tid];
    __syncthreads();

    if (px >= npix) return;
    int t = px;
    int h, w;
    if (t < Wo) { h = 0; w = t; }
    else if (t < 2 * Wo) { h = Ho - 1; w = t - Wo; }
    else { int t2 = t - 2 * Wo; h = 1 + (t2 >> 1); w = (t2 & 1) ? (Wo - 1) : 0; }

    float acc[8];
#pragma unroll
    for (int j = 0; j < 8; ++j) acc[j] = cb[cg * 8 + j];

    for (int di = 0; di < 3; ++di)
        for (int dj = 0; dj < 3; ++dj) {
            int p = h - 1 + di, q = w - 1 + dj;
            if (p < 0 || p >= Ho || q < 0 || q >= Wo) continue;
            int ip = p >> 1, pp = p & 1, iq = q >> 1, qq = q & 1;
            float inv[32];
#pragma unroll
            for (int ci = 0; ci < 32; ++ci)
                inv[ci] = in[((size_t)(b * 32 + ci) * Hi + ip) * Wi + iq];
            const float* dwb = &s_dw[(pp * 2 + qq) * 32];
            const float* cwt = &s_cw[(di * 3 + dj) * 1024 + cg * 8];
#pragma unroll 4
            for (int m = 0; m < 32; ++m) {
                float t1m = s_db[m];
#pragma unroll
                for (int ci = 0; ci < 32; ++ci) t1m += inv[ci] * dwb[m * 128 + ci];
                const float* cwm = cwt + m * 32;
#pragma unroll
                for (int j = 0; j < 8; ++j) acc[j] += t1m * cwm[j];
            }
        }

    {
        const size_t plane = (size_t)Ho * Wo;
        size_t ob = ((size_t)(b * 32 + cg * 8)) * plane + (size_t)h * Wo + w;
#pragma unroll
        for (int j = 0; j < 8; ++j) {
            float v = acc[j];
            if (MODE == 2) v *= orig[ob + (size_t)j * plane];
            out[ob + (size_t)j * plane] = v;
        }
    }
}

// ---------------- host launch ----------------
extern "C" void kernel_launch(void* const* d_in, const int* in_sizes, int n_in,
                              void* d_out, int out_size) {
    const float* x = (const float*)d_in[0];
    const float* w1 = (const float*)d_in[1];   const float* b1 = (const float*)d_in[2];
    const float* w2 = (const float*)d_in[3];   const float* b2 = (const float*)d_in[4];
    const float* w3 = (const float*)d_in[5];   const float* b3 = (const float*)d_in[6];
    const float* w4 = (const float*)d_in[7];   const float* b4 = (const float*)d_in[8];
    const float* w5 = (const float*)d_in[9];   const float* b5 = (const float*)d_in[10];
    const float* w6 = (const float*)d_in[11];  const float* b6 = (const float*)d_in[12];
    const float* w7 = (const float*)d_in[13];  const float* b7 = (const float*)d_in[14];
    const float* dw1 = (const float*)d_in[15]; const float* db1 = (const float*)d_in[16];
    const float* dw2 = (const float*)d_in[17]; const float* db2 = (const float*)d_in[18];
    const float* dw3 = (const float*)d_in[19]; const float* db3 = (const float*)d_in[20];
    float* outp = (float*)d_out;

    void* p;
    cudaGetSymbolAddress(&p, g_s1);   float* s1 = (float*)p;
    cudaGetSymbolAddress(&p, g_s2);   float* s2 = (float*)p;
    cudaGetSymbolAddress(&p, g_q1);   float* q1 = (float*)p;
    cudaGetSymbolAddress(&p, g_q2);   float* q2 = (float*)p;
    cudaGetSymbolAddress(&p, g_e1);   float* e1 = (float*)p;
    cudaGetSymbolAddress(&p, g_e2);   float* e2 = (float*)p;
    cudaGetSymbolAddress(&p, g_w3x3); float* wt = (float*)p;
    cudaGetSymbolAddress(&p, g_ck);   float* ckp = (float*)p;
    cudaGetSymbolAddress(&p, g_cb);   float* cbp = (float*)p;

    dim3 blk(32, 8);

    // stats + keff first so conv1_5x5 stays the 4th launch (ncu capture slot)
    stats_op_kernel<<<dim3(16, 16, B_ * C_), blk>>>(x);
    stats2_kernel<<<21, 256>>>(w1);
    keff_kernel<<<dim3(B_, 33), 32>>>(w1, b1);
    conv1_5x5_kernel<<<dim3(8, 64, B_), blk>>>(x, s1);
    conv1_strip_kernel<<<dim3(64, B_), blk>>>(x, w1, b1, s1);

    // remaining weight prep
    prep_w_kernel<<<3, 256>>>(w2, w3, w4);
    ck_kernel<<<dim3(33, 3), 32>>>(dw1, db1, w5, b5, dw2, db2, w6, b6, dw3, db3, w7, b7);

    // conv2 + pool: s1 -> q1 (128^2)
    conv3x3_kernel<1><<<dim3(8, 32, B_), blk>>>(s1, wt + 0 * 9216, b2, q1, 256, 256);
    // conv3 + pool: q1 -> e1 (64^2)
    conv3x3_kernel<1><<<dim3(4, 16, B_), blk>>>(q1, wt + 1 * 9216, b3, e1, 128, 128);
    // conv4: e1 -> e2 (64^2)
    conv3x3_kernel<0><<<dim3(2, 8, B_), blk>>>(e1, wt + 2 * 9216, b4, e2, 64, 64);

    // stage1: composed deconv1+conv5: e2 (64^2) -> q2 (128^2)
    bconv_kernel<0><<<dim3(8, B_), 256>>>(e2, dw1, db1, w5, b5, q2, 64, 64, nullptr);
    dconv_kernel<0><<<dim3(2, 32, B_), blk>>>(e2, ckp + 0 * 16384, cbp + 0, q2, 64, 64, nullptr);
    // stage2: composed deconv2+conv6: q2 (128^2) -> s2 (256^2)
    bconv_kernel<0><<<dim3(16, B_), 256>>>(q2, dw2, db2, w6, b6, s2, 128, 128, nullptr);
    dconv_kernel<0><<<dim3(4, 64, B_), blk>>>(q2, ckp + 1 * 16384, cbp + 32, s2, 128, 128, nullptr);
    // stage3: composed deconv3+conv7 (+ orig mult): s2 (256^2) -> out (512^2)
    bconv_kernel<2><<<dim3(32, B_), 256>>>(s2, dw3, db3, w7, b7, outp, 256, 256, x);
    dconv_kernel<2><<<dim3(8, 128, B_), blk>>>(s2, ckp + 2 * 16384, cbp + 64, outp, 256, 256, x);
}

// round 16
// speedup vs baseline: 1.0556x; 1.0049x over previous
#include <cuda_runtime.h>

#define B_ 4
#define C_ 32
#define H_ 512
#define W_ 512

// ---------------- scratch (device globals; no runtime allocation) ----------------
static __device__ float g_s1[(size_t)B_ * C_ * 256 * 256];
static __device__ float g_s2[(size_t)B_ * C_ * 256 * 256];
static __device__ float g_q1[(size_t)B_ * C_ * 128 * 128];
static __device__ float g_q2[(size_t)B_ * C_ * 128 * 128];
static __device__ float g_e1[(size_t)B_ * C_ * 64 * 64];
static __device__ float g_e2[(size_t)B_ * C_ * 64 * 64];
static __device__ float g_partS[20 * 8192];
static __device__ float g_partQ[20 * 8192];
static __device__ float g_norm[40];                         // (mean, inv_std) per (b, branch)
static __device__ float g_keff[(size_t)B_ * 32 * 25 * 32];  // composed 5x5 kernels [b][ci][tap][co]
static __device__ float g_c1[B_ * 32];                      // conv1 constant term
static __device__ float g_ws[160];                          // sum of w1 over (ci,taps): [co][br]
static __device__ float g_w3x3[3 * 9216];                   // transposed [ci][tap][co] for w2..w4
static __device__ float g_ck[3 * 16384];                    // composed deconv+conv: [st][ci][phw][cell][co]
static __device__ float g_cb[96];                           // composed bias per stage [st][co]

// ---------------- packed f32x2 helpers ----------------
typedef unsigned long long u64;

__device__ __forceinline__ u64 pk(float v) {
    u64 r; asm("mov.b64 %0, {%1, %1};" : "=l"(r) : "f"(v)); return r;
}
__device__ __forceinline__ u64 pk2(float a, float b) {
    u64 r; asm("mov.b64 %0, {%1, %2};" : "=l"(r) : "f"(a), "f"(b)); return r;
}
__device__ __forceinline__ void fma2(u64& d, u64 a, u64 b) {
    asm("fma.rn.f32x2 %0, %1, %2, %0;" : "+l"(d) : "l"(a), "l"(b));
}
__device__ __forceinline__ void unpk(u64 v, float& lo, float& hi) {
    asm("mov.b64 {%0, %1}, %2;" : "=f"(lo), "=f"(hi) : "l"(v));
}

// ---------------- cp.async helpers ----------------
__device__ __forceinline__ unsigned scvt(const void* p) {
    return (unsigned)__cvta_generic_to_shared(p);
}
__device__ __forceinline__ void cpa4f(unsigned s, const float* g) {
    asm volatile("cp.async.ca.shared.global [%0], [%1], 4;" :: "r"(s), "l"(g));
}
__device__ __forceinline__ void cpa16(unsigned s, const float* g, bool ok) {
    asm volatile("cp.async.cg.shared.global [%0], [%1], 16, %2;"
                 :: "r"(s), "l"(g), "r"(ok ? 16 : 0));
}
__device__ __forceinline__ void cpa16f(unsigned s, const float* g) {
    asm volatile("cp.async.cg.shared.global [%0], [%1], 16;" :: "r"(s), "l"(g));
}
#define CP_COMMIT() asm volatile("cp.async.commit_group;" ::: "memory")
#define CP_WAIT0()  asm volatile("cp.async.wait_group 0;" ::: "memory")

// ---------------- shared edge-operator math ----------------
__device__ __forceinline__ void edge5(float a00, float a01, float a02,
                                      float a10, float a11, float a12,
                                      float a20, float a21, float a22, float o[5]) {
    float sxv = -a00 + a02 - 2.f * a10 + 2.f * a12 - a20 + a22;
    float syv = -a00 - 2.f * a01 - a02 + a20 + 2.f * a21 + a22;
    o[0] = 0.5f * (sxv + syv);
    float cxv = -3.f * a00 + 3.f * a02 - 10.f * a10 + 10.f * a12 - 3.f * a20 + 3.f * a22;
    float cyv = -3.f * a00 - 10.f * a01 - 3.f * a02 + 3.f * a20 + 10.f * a21 + 3.f * a22;
    o[1] = 0.5f * (cxv + cyv);
    o[2] = 2.f * a00 + 2.f * a02 - 8.f * a11 + 2.f * a20 + 2.f * a22;
    o[3] = 0.5f * ((-a00 + a11) + (-a01 + a10));
    float pxv = a00 + a01 + a02 - a20 - a21 - a22;
    float pyv = -a00 + a02 - a10 + a12 - a20 + a22;
    o[4] = 0.5f * (pxv + pyv);
}

static __device__ const float G_[5][3][3] = {
    {{-1.f, -1.f, 0.f}, {-1.f, 0.f, 1.f}, {0.f, 1.f, 1.f}},
    {{-3.f, -5.f, 0.f}, {-5.f, 0.f, 5.f}, {0.f, 5.f, 3.f}},
    {{2.f, 0.f, 2.f}, {0.f, -8.f, 0.f}, {2.f, 0.f, 2.f}},
    {{-0.5f, -0.5f, 0.f}, {0.5f, 0.5f, 0.f}, {0.f, 0.f, 0.f}},
    {{0.f, 0.5f, 1.f}, {-0.5f, 0.f, 0.5f}, {-1.f, -0.5f, 0.f}}
};

__device__ __forceinline__ int refl(int i, int n) {
    return i < 0 ? -i : (i >= n ? 2 * n - 2 - i : i);
}

// ---------------- fused operator + partial stats (4 px/thread) ----------------
__global__ void stats_op_kernel(const float* __restrict__ x) {
    __shared__ float sx[34 * 34];
    __shared__ float red[8][10];
    const int tx = threadIdx.x, ty = threadIdx.y;
    const int tid = ty * 32 + tx;
    const int w0 = blockIdx.x * 32, h0 = blockIdx.y * 32;
    const int bc = blockIdx.z;
    const int b = bc >> 5, c = bc & 31;
    const float* xp = x + (size_t)bc * H_ * W_;

    for (int i = tid; i < 1156; i += 256) {
        int r = i / 34, cl = i - r * 34;
        sx[i] = xp[refl(h0 - 1 + r, H_) * W_ + refl(w0 - 1 + cl, W_)];
    }
    __syncthreads();

    float s[5] = {0.f, 0.f, 0.f, 0.f, 0.f}, q[5] = {0.f, 0.f, 0.f, 0.f, 0.f};
#pragma unroll
    for (int k = 0; k < 4; ++k) {
        const int r = ty * 4 + k;
        float o[5];
        edge5(sx[r * 34 + tx], sx[r * 34 + tx + 1], sx[r * 34 + tx + 2],
              sx[(r + 1) * 34 + tx], sx[(r + 1) * 34 + tx + 1], sx[(r + 1) * 34 + tx + 2],
              sx[(r + 2) * 34 + tx], sx[(r + 2) * 34 + tx + 1], sx[(r + 2) * 34 + tx + 2], o);
#pragma unroll
        for (int br = 0; br < 5; ++br) {
            s[br] += o[br];
            q[br] += o[br] * o[br];
        }
    }

#pragma unroll
    for (int br = 0; br < 5; ++br) {
        float sv = s[br], qv = q[br];
#pragma unroll
        for (int off = 16; off; off >>= 1) {
            sv += __shfl_down_sync(0xffffffffu, sv, off);
            qv += __shfl_down_sync(0xffffffffu, qv, off);
        }
        if (tx == 0) { red[ty][br] = sv; red[ty][5 + br] = qv; }
    }
    __syncthreads();
    if (tid < 10) {
        float t = 0.f;
#pragma unroll
        for (int w = 0; w < 8; ++w) t += red[w][tid];
        int tile = blockIdx.x + 16 * blockIdx.y + 256 * c;
        if (tid < 5) g_partS[(b * 5 + tid) * 8192 + tile] = t;
        else         g_partQ[(b * 5 + tid - 5) * 8192 + tile] = t;
    }
}

// stage2 (blocks 0-19) + w1 sums (block 20)
__global__ void stats2_kernel(const float* __restrict__ w1) {
    if (blockIdx.x == 20) {
        int t = threadIdx.x;
        if (t < 160) {
            int co = t / 5, br = t % 5;
            float s = 0.f;
            for (int ci = 0; ci < 32; ++ci) {
                const float* wq = &w1[((size_t)co * 160 + br * 32 + ci) * 9];
#pragma unroll
                for (int u = 0; u < 9; ++u) s += wq[u];
            }
            g_ws[t] = s;
        }
        return;
    }
    __shared__ float rs[256], rq[256];
    const int seg = blockIdx.x, t = threadIdx.x;
    float s = 0.f, q = 0.f;
    for (int i = t; i < 8192; i += 256) {
        s += g_partS[seg * 8192 + i];
        q += g_partQ[seg * 8192 + i];
    }
    rs[t] = s; rq[t] = q;
    __syncthreads();
    for (int st = 128; st > 0; st >>= 1) {
        if (t < st) { rs[t] += rs[t + st]; rq[t] += rq[t + st]; }
        __syncthreads();
    }
    if (t == 0) {
        const double N = (double)32 * H_ * W_;
        double mean = (double)rs[0] / N;
        double var = (double)rq[0] / N - mean * mean;
        if (var < 1e-30) var = 1e-30;
        g_norm[seg * 2 + 0] = (float)mean;
        g_norm[seg * 2 + 1] = (float)(1.0 / sqrt(var));
    }
}

// ---------------- weight prep: transpose w2..w4 ----------------
__global__ void prep_w_kernel(const float* w2, const float* w3, const float* w4) {
    const float* src[3] = {w2, w3, w4};
    const float* s = src[blockIdx.x];
    float* dst = g_w3x3 + blockIdx.x * 9216;
    for (int i = threadIdx.x; i < 9216; i += 256) {
        int ci = i / 288, rem = i - ci * 288;
        int tap = rem >> 5, co = rem & 31;
        dst[i] = s[((size_t)co * 32 + ci) * 9 + tap];
    }
}

// keff (ci < 32) + c1 constant (ci == 32)
__global__ void keff_kernel(const float* __restrict__ w1, const float* __restrict__ b1) {
    const int b = blockIdx.x, ci = blockIdx.y, co = threadIdx.x;
    if (ci == 32) {
        float s = b1[co];
#pragma unroll
        for (int br = 0; br < 5; ++br) {
            float m = g_norm[(b * 5 + br) * 2], ns = g_norm[(b * 5 + br) * 2 + 1];
            s -= m * ns * g_ws[co * 5 + br];
        }
        g_c1[b * 32 + co] = s;
        return;
    }
    float k[25];
#pragma unroll
    for (int t = 0; t < 25; ++t) k[t] = 0.f;
#pragma unroll
    for (int br = 0; br < 5; ++br) {
        float ns = g_norm[(b * 5 + br) * 2 + 1];
#pragma unroll
        for (int ui = 0; ui < 3; ++ui)
#pragma unroll
            for (int uj = 0; uj < 3; ++uj) {
                float wv = ns * w1[(((size_t)co * 160 + br * 32 + ci) * 3 + ui) * 3 + uj];
#pragma unroll
                for (int vi = 0; vi < 3; ++vi)
#pragma unroll
                    for (int vj = 0; vj < 3; ++vj)
                        k[(ui + vi) * 5 + (uj + vj)] += wv * G_[br][vi][vj];
            }
    }
    for (int t = 0; t < 25; ++t)
        g_keff[(((size_t)b * 32 + ci) * 25 + t) * 32 + co] = k[t];
}

// ---------------- composed deconv2x2(s2)+conv3x3 weights ----------------
__global__ void ck_kernel(const float* dw1, const float* db1, const float* w5, const float* b5,
                          const float* dw2, const float* db2, const float* w6, const float* b6,
                          const float* dw3, const float* db3, const float* w7, const float* b7) {
    const int st = blockIdx.y;
    const float* dw = st == 0 ? dw1 : st == 1 ? dw2 : dw3;
    const float* db = st == 0 ? db1 : st == 1 ? db2 : db3;
    const float* cw = st == 0 ? w5 : st == 1 ? w6 : w7;
    const float* cb = st == 0 ? b5 : st == 1 ? b6 : b7;
    const int ci = blockIdx.x, co = threadIdx.x;
    if (ci == 32) {
        float s = cb[co];
        for (int m = 0; m < 32; ++m) {
            float ws = 0.f;
#pragma unroll
            for (int t = 0; t < 9; ++t) ws += cw[((size_t)co * 32 + m) * 9 + t];
            s += db[m] * ws;
        }
        g_cb[st * 32 + co] = s;
        return;
    }
    float K[4][4];
#pragma unroll
    for (int i = 0; i < 4; ++i)
#pragma unroll
        for (int j = 0; j < 4; ++j) K[i][j] = 0.f;
    for (int m = 0; m < 32; ++m) {
        float dv[2][2];
#pragma unroll
        for (int pp = 0; pp < 2; ++pp)
#pragma unroll
            for (int qq = 0; qq < 2; ++qq)
                dv[pp][qq] = dw[(((size_t)ci * 32 + m) * 2 + pp) * 2 + qq];
        const float* cwm = &cw[((size_t)co * 32 + m) * 9];
#pragma unroll
        for (int ph = 0; ph < 2; ++ph)
#pragma unroll
            for (int pw = 0; pw < 2; ++pw)
#pragma unroll
                for (int di = 0; di < 3; ++di) {
                    int sh = di + 1 - ph, r = sh >> 1, pp = sh & 1;
#pragma unroll
                    for (int dj = 0; dj < 3; ++dj) {
                        int sw = dj + 1 - pw, c = sw >> 1, qq = sw & 1;
                        K[ph * 2 + pw][r * 2 + c] += dv[pp][qq] * cwm[di * 3 + dj];
                    }
                }
    }
#pragma unroll
    for (int phw = 0; phw < 4; ++phw)
#pragma unroll
        for (int cell = 0; cell < 4; ++cell)
            g_ck[st * 16384 + ((ci * 4 + phw) * 4 + cell) * 32 + co] = K[phw][cell];
}

// ---------------- conv1 interior: composed 5x5 conv + thread-local 2x2 pool -----------
// tile 64w x 8h; thread = 2x2 pixels x 16 co. grid (8, 64, B), block (32,8)
__global__ void __launch_bounds__(256, 2)
conv1_5x5_kernel(const float* __restrict__ x, float* __restrict__ out) {
    constexpr int RW = 72;
    constexpr int CT = 12 * RW;
    __shared__ __align__(16) float s_x[2][4 * CT];
    __shared__ __align__(16) float s_w[2][3200];
    const int tx = threadIdx.x, ty = threadIdx.y, tid = ty * 32 + tx;
    const int w0 = 2 + blockIdx.x * 64, h0 = 2 + blockIdx.y * 8;
    const int b = blockIdx.z;
    const int gr = ty & 3, ch = ty >> 2;
    const bool fast = (blockIdx.x < 7) && (blockIdx.y < 63);

    auto issue = [&](int ci0, int buf) {
        const float* kw = g_keff + (size_t)(b * 32 + ci0) * 800;
        if (fast) {
#pragma unroll
            for (int k = 0; k < 7; ++k) {
                int i = tid + k * 256;
                if (i < 816) {
                    int cc = i / 204, rem = i - cc * 204;
                    int r = rem / 17, p = rem - r * 17;
                    cpa16f(scvt(&s_x[buf][cc * CT + r * RW + p * 4]),
                           &x[((size_t)(b * 32 + ci0 + cc) * 512 + (h0 - 2 + r)) * 512 + (w0 - 2) + p * 4]);
                } else if (i < 1616) {
                    int j = i - 816;
                    cpa16f(scvt(&s_w[buf][j * 4]), kw + j * 4);
                }
            }
        } else {
#pragma unroll
            for (int k = 0; k < 13; ++k) {
                int i = tid + k * 256;
                if (i < 3264) {
                    int cc = i / 816, rem = i - cc * 816;
                    int r = rem / 68, cl = rem - r * 68;
                    cpa4f(scvt(&s_x[buf][cc * CT + r * RW + cl]),
                          &x[((size_t)(b * 32 + ci0 + cc) * 512 + refl(h0 - 2 + r, 512)) * 512 + refl(w0 - 2 + cl, 512)]);
                }
            }
#pragma unroll
            for (int k = 0; k < 4; ++k) {
                int i = tid + k * 256;
                if (i < 800)
                    cpa16f(scvt(&s_w[buf][i * 4]), kw + i * 4);
            }
        }
    };
    issue(0, 0);
    CP_COMMIT();

    u64 acc[2][2][8];
#pragma unroll
    for (int j = 0; j < 8; ++j) {
        u64 cv = pk2(g_c1[b * 32 + ch * 16 + 2 * j], g_c1[b * 32 + ch * 16 + 2 * j + 1]);
        acc[0][0][j] = cv; acc[0][1][j] = cv;
        acc[1][0][j] = cv; acc[1][1][j] = cv;
    }

    int buf = 0;
    for (int ci0 = 0; ci0 < 32; ci0 += 4) {
        CP_WAIT0();
        __syncthreads();
        if (ci0 + 4 < 32) { issue(ci0 + 4, buf ^ 1); CP_COMMIT(); }
#pragma unroll
        for (int cc = 0; cc < 4; ++cc) {
            const float* ib = &s_x[buf][cc * CT + (2 * gr) * RW + 2 * tx];
            const float* wb = &s_w[buf][cc * 800];
            float rowf[2][6];
            {
                const float2* rp = (const float2*)ib;
                float2 a0 = rp[0], a1 = rp[1], a2 = rp[2];
                rowf[0][0] = a0.x; rowf[0][1] = a0.y;
                rowf[0][2] = a1.x; rowf[0][3] = a1.y;
                rowf[0][4] = a2.x; rowf[0][5] = a2.y;
            }
#pragma unroll
            for (int ti = 0; ti < 5; ++ti) {
                {
                    const float2* rp = (const float2*)(ib + (ti + 1) * RW);
                    float2 a0 = rp[0], a1 = rp[1], a2 = rp[2];
                    float* nx = rowf[(ti + 1) & 1];
                    nx[0] = a0.x; nx[1] = a0.y;
                    nx[2] = a1.x; nx[3] = a1.y;
                    nx[4] = a2.x; nx[5] = a2.y;
                }
                const float* cur = rowf[ti & 1];
                const float* nxt = rowf[(ti + 1) & 1];
#pragma unroll
                for (int tj = 0; tj < 5; ++tj) {
                    u64 v00 = pk(cur[tj]);
                    u64 v01 = pk(cur[tj + 1]);
                    u64 v10 = pk(nxt[tj]);
                    u64 v11 = pk(nxt[tj + 1]);
                    const u64* wq = (const u64*)(wb + (ti * 5 + tj) * 32) + ch * 8;
#pragma unroll
                    for (int j = 0; j < 8; ++j) {
                        u64 q = wq[j];
                        fma2(acc[0][0][j], v00, q);
                        fma2(acc[0][1][j], v01, q);
                        fma2(acc[1][0][j], v10, q);
                        fma2(acc[1][1][j], v11, q);
                    }
                }
            }
        }
        buf ^= 1;
    }

    const int hp = (h0 >> 1) + gr;
    const int wp = (w0 >> 1) + tx;
    const size_t plane = 65536;
    if (hp < 255 && wp < 255) {
        size_t ob = ((size_t)b * 32 + ch * 16) * plane + (size_t)hp * 256 + wp;
#pragma unroll
        for (int j = 0; j < 8; ++j) {
            float a, bb, c, d, e, f, g, h;
            unpk(acc[0][0][j], a, bb);
            unpk(acc[0][1][j], c, d);
            unpk(acc[1][0][j], e, f);
            unpk(acc[1][1][j], g, h);
            float m0 = fmaxf(fmaxf(a, c), fmaxf(e, g));
            float m1 = fmaxf(fmaxf(bb, d), fmaxf(f, h));
            out[ob + (size_t)(2 * j) * plane] = m0;
            out[ob + (size_t)(2 * j + 1) * plane] = m1;
        }
    }
}

// ---------------- conv1 border strips (2 conv rows/cols only) ----------------
__global__ void __launch_bounds__(256, 2)
conv1_strip_kernel(const float* __restrict__ x, const float* __restrict__ wgt,
                   const float* __restrict__ bias, float* __restrict__ out) {
    __shared__ __align__(16) float s_x[2][216];
    __shared__ __align__(16) float s_op[5][136];
    __shared__ __align__(16) float s_w[2][1440];
    __shared__ float s_nm[5], s_ns[5];
    const int tx = threadIdx.x, ty = threadIdx.y, tid = ty * 32 + tx;
    const int b = blockIdx.y;
    int si = blockIdx.x;
    const bool vert = si >= 32;
    si &= 31;
    const int longB = (si & 15) * 32;
    const int shortB = (si < 16) ? 0 : 510;

    if (tid < 5) {
        s_nm[tid] = g_norm[(b * 5 + tid) * 2 + 0];
        s_ns[tid] = g_norm[(b * 5 + tid) * 2 + 1];
    }

    if (tid < 216) {
        int r = tid / 36, c = tid - r * 36;
        int gh = vert ? (longB - 2 + c) : (shortB - 2 + r);
        int gw = vert ? (shortB - 2 + r) : (longB - 2 + c);
        s_x[0][tid] = x[((size_t)b * 32 * 512 + refl(gh, 512)) * 512 + refl(gw, 512)];
    }
#pragma unroll
    for (int k = 0; k < 6; ++k) {
        int i = tid + k * 256;
        if (i < 1440) {
            int br = i / 288, rem = i - br * 288;
            int tap = rem >> 5, co = rem & 31;
            s_w[0][i] = wgt[((size_t)co * 160 + br * 32) * 9 + tap];
        }
    }
    __syncthreads();

    u64 acc[2][2];
#pragma unroll
    for (int q = 0; q < 2; ++q) {
        u64 bv = pk2(bias[ty * 4 + 2 * q], bias[ty * 4 + 2 * q + 1]);
        acc[0][q] = bv; acc[1][q] = bv;
    }

    int buf = 0;
    for (int ci = 0; ci < 32; ++ci) {
        const bool more = (ci + 1 < 32);
        float rx, rw[6];
        if (more) {
            if (tid < 216) {
                int r = tid / 36, c = tid - r * 36;
                int gh = vert ? (longB - 2 + c) : (shortB - 2 + r);
                int gw = vert ? (shortB - 2 + r) : (longB - 2 + c);
                rx = x[(((size_t)b * 32 + ci + 1) * 512 + refl(gh, 512)) * 512 + refl(gw, 512)];
            }
#pragma unroll
            for (int k = 0; k < 6; ++k) {
                int i = tid + k * 256;
                if (i < 1440) {
                    int br = i / 288, rem = i - br * 288;
                    int tap = rem >> 5, co = rem & 31;
                    rw[k] = wgt[((size_t)co * 160 + br * 32 + ci + 1) * 9 + tap];
                }
            }
        }
        if (tid < 136) {
            int sp = tid / 34, lp = tid - sp * 34;
            int h = vert ? (longB - 1 + lp) : (shortB - 1 + sp);
            int w = vert ? (shortB - 1 + sp) : (longB - 1 + lp);
            float o[5] = {0.f, 0.f, 0.f, 0.f, 0.f};
            if (h >= 0 && h < 512 && w >= 0 && w < 512) {
                float a[3][3];
#pragma unroll
                for (int dh = 0; dh < 3; ++dh)
#pragma unroll
                    for (int dw = 0; dw < 3; ++dw) {
                        int r = vert ? (sp + dw) : (sp + dh);
                        int c = vert ? (lp + dh) : (lp + dw);
                        a[dh][dw] = s_x[buf][r * 36 + c];
                    }
                edge5(a[0][0], a[0][1], a[0][2], a[1][0], a[1][1], a[1][2],
                      a[2][0], a[2][1], a[2][2], o);
#pragma unroll
                for (int k = 0; k < 5; ++k) o[k] = (o[k] - s_nm[k]) * s_ns[k];
            }
#pragma unroll
            for (int k = 0; k < 5; ++k) s_op[k][tid] = o[k];
        }
        __syncthreads();

#pragma unroll
        for (int br = 0; br < 5; ++br) {
#pragma unroll
            for (int ds = 0; ds < 3; ++ds)
#pragma unroll
                for (int dl = 0; dl < 3; ++dl) {
                    int tap = vert ? (dl * 3 + ds) : (ds * 3 + dl);
                    const u64* wq = (const u64*)(&s_w[buf][br * 288 + tap * 32]) + ty * 2;
                    u64 q0 = wq[0], q1 = wq[1];
#pragma unroll
                    for (int s = 0; s < 2; ++s) {
                        u64 v = pk(s_op[br][(s + ds) * 34 + tx + dl]);
                        fma2(acc[s][0], v, q0);
                        fma2(acc[s][1], v, q1);
                    }
                }
        }
        if (more) {
            if (tid < 216) s_x[buf ^ 1][tid] = rx;
#pragma unroll
            for (int k = 0; k < 6; ++k) {
                int i = tid + k * 256;
                if (i < 1440) s_w[buf ^ 1][i] = rw[k];
            }
        }
        __syncthreads();
        buf ^= 1;
    }

    const size_t plane = 65536;
    const int hp = vert ? ((longB + tx) >> 1) : (shortB >> 1);
    const int wp = vert ? (shortB >> 1) : ((longB + tx) >> 1);
#pragma unroll
    for (int q = 0; q < 2; ++q) {
        float l0, u0, l1, u1;
        unpk(acc[0][q], l0, u0);
        unpk(acc[1][q], l1, u1);
        float m0 = fmaxf(l0, l1), m1 = fmaxf(u0, u1);
        m0 = fmaxf(m0, __shfl_xor_sync(0xffffffffu, m0, 1));
        m1 = fmaxf(m1, __shfl_xor_sync(0xffffffffu, m1, 1));
        if (!(tx & 1)) {
            int co = ty * 4 + 2 * q;
            out[((size_t)(b * 32 + co) * plane) + (size_t)hp * 256 + wp] = m0;
            out[((size_t)(b * 32 + co + 1) * plane) + (size_t)hp * 256 + wp] = m1;
        }
    }
}

// ---------------- conv3x3 + fused pool, 2x2 px/thread (conv2, conv3) ----------------
// tile 64w x 8h -> pooled 32x4. grid (Ww/64, Hh/8, B), block (32,8)
__global__ void __launch_bounds__(256, 2)
conv3x3p_kernel(const float* __restrict__ in, const float* __restrict__ wgt,
                const float* __restrict__ bias, float* __restrict__ out,
                int Hh, int Ww) {
    constexpr int RW = 72;
    constexpr int CT = 10 * RW;        // per-ci tile (10 rows)
    __shared__ __align__(16) float s_in[2][4 * CT];
    __shared__ __align__(16) float s_w[9216];
    const int tx = threadIdx.x, ty = threadIdx.y, tid = ty * 32 + tx;
    const int w0 = blockIdx.x * 64, h0 = blockIdx.y * 8;
    const int b = blockIdx.z;
    const int gr = ty & 3, ch = ty >> 2;

    // weights: 2304 16B packets, 9 per thread
    {
        const float* g = wgt + tid * 4;
        unsigned sdst = scvt(&s_w[tid * 4]);
#pragma unroll
        for (int k = 0; k < 9; ++k) cpa16f(sdst + k * 4096, g + k * 1024);
    }
    auto issue = [&](int ci0, int buf) {
        // 720 packets: cc(4) x row(10) x packet(18), row origin gw = w0-4
#pragma unroll
        for (int k = 0; k < 3; ++k) {
            int i = tid + k * 256;
            if (i < 720) {
                int cc = i / 180, rem = i - cc * 180;
                int r = rem / 18, pi = rem - r * 18;
                int gh = h0 - 1 + r;
                int gw0 = w0 - 4 + pi * 4;
                bool ok = (gh >= 0 && gh < Hh && gw0 >= 0 && gw0 + 4 <= Ww);
                const float* g = ok ? &in[(((size_t)b * 32 + ci0 + cc) * Hh + gh) * Ww + gw0] : in;
                cpa16(scvt(&s_in[buf][cc * CT + r * RW + pi * 4]), g, ok);
            }
        }
    };
    issue(0, 0);
    CP_COMMIT();

    u64 acc[2][2][8];
#pragma unroll
    for (int j = 0; j < 8; ++j) {
        u64 bv = pk2(bias[ch * 16 + 2 * j], bias[ch * 16 + 2 * j + 1]);
        acc[0][0][j] = bv; acc[0][1][j] = bv;
        acc[1][0][j] = bv; acc[1][1][j] = bv;
    }

    int buf = 0;
    for (int ci0 = 0; ci0 < 32; ci0 += 4) {
        CP_WAIT0();
        __syncthreads();
        if (ci0 + 4 < 32) { issue(ci0 + 4, buf ^ 1); CP_COMMIT(); }
#pragma unroll
        for (int cc = 0; cc < 4; ++cc) {
            // thread covers output cols w0+2tx, w0+2tx+1; row window = 4 rows (rows idx 2gr..2gr+4)
            // local col l corresponds to gw = w0-4+... base load from element (2tx+2): gw=w0+2tx-2
            const float* ib = &s_in[buf][cc * CT + (2 * gr) * RW + 2 * tx + 2];
            const float* wb = &s_w[(ci0 + cc) * 288];
            float rowf[2][6];
            {
                const float2* rp = (const float2*)ib;
                float2 a0 = rp[0], a1 = rp[1], a2 = rp[2];
                rowf[0][0] = a0.x; rowf[0][1] = a0.y;
                rowf[0][2] = a1.x; rowf[0][3] = a1.y;
                rowf[0][4] = a2.x; rowf[0][5] = a2.y;
            }
#pragma unroll
            for (int di = 0; di < 3; ++di) {
                {
                    const float2* rp = (const float2*)(ib + (di + 1) * RW);
                    float2 a0 = rp[0], a1 = rp[1], a2 = rp[2];
                    float* nx = rowf[(di + 1) & 1];
                    nx[0] = a0.x; nx[1] = a0.y;
                    nx[2] = a1.x; nx[3] = a1.y;
                    nx[4] = a2.x; nx[5] = a2.y;
                }
                const float* cur = rowf[di & 1];
                const float* nxt = rowf[(di + 1) & 1];
#pragma unroll
                for (int dj = 0; dj < 3; ++dj) {
                    // output col c: input gw = w0+2tx+c+dj-1 -> local = (gw - (w0+2tx-2)) = 1+dj+c
                    u64 v00 = pk(cur[1 + dj]);
                    u64 v01 = pk(cur[2 + dj]);
                    u64 v10 = pk(nxt[1 + dj]);
                    u64 v11 = pk(nxt[2 + dj]);
                    const u64* wq = (const u64*)(wb + (di * 3 + dj) * 32) + ch * 8;
#pragma unroll
                    for (int j = 0; j < 8; ++j) {
                        u64 q = wq[j];
                        fma2(acc[0][0][j], v00, q);
                        fma2(acc[0][1][j], v01, q);
                        fma2(acc[1][0][j], v10, q);
                        fma2(acc[1][1][j], v11, q);
                    }
                }
            }
        }
        buf ^= 1;
    }

    // thread-local 2x2 pool
    const int Hp = Hh >> 1, Wp = Ww >> 1;
    const size_t plane = (size_t)Hp * Wp;
    const int hp = (h0 >> 1) + gr;
    const int wp = (w0 >> 1) + tx;
    size_t ob = ((size_t)b * 32 + ch * 16) * plane + (size_t)hp * Wp + wp;
#pragma unroll
    for (int j = 0; j < 8; ++j) {
        float a, bb, c, d, e, f, g, h;
        unpk(acc[0][0][j], a, bb);
        unpk(acc[0][1][j], c, d);
        unpk(acc[1][0][j], e, f);
        unpk(acc[1][1][j], g, h);
        float m0 = fmaxf(fmaxf(a, c), fmaxf(e, g));
        float m1 = fmaxf(fmaxf(bb, d), fmaxf(f, h));
        out[ob + (size_t)(2 * j) * plane] = m0;
        out[ob + (size_t)(2 * j + 1) * plane] = m1;
    }
}

// ---------------- conv3x3 CIN=32 (zero pad), plain (conv4) ----------------
__global__ void __launch_bounds__(256, 3)
conv3x3_kernel(const float* __restrict__ in, const float* __restrict__ wgt,
               const float* __restrict__ bias, float* __restrict__ out,
               int Hh, int Ww) {
    constexpr int ROWW = 40;
    constexpr int CH = 4 * 10 * ROWW;
    __shared__ __align__(16) float s_in[2][CH];
    __shared__ __align__(16) float s_w[9216];
    const int tx = threadIdx.x, ty = threadIdx.y, tid = ty * 32 + tx;
    const int w0 = blockIdx.x * 32, h0 = blockIdx.y * 8;
    const int b = blockIdx.z;
    const int gr = ty & 3, ch = ty >> 2;

    {
        const float* g = wgt + tid * 4;
        unsigned sdst = scvt(&s_w[tid * 4]);
#pragma unroll
        for (int k = 0; k < 9; ++k) cpa16f(sdst + k * 4096, g + k * 1024);
    }
    auto issue = [&](int ci0, int buf) {
#pragma unroll
        for (int k = 0; k < 2; ++k) {
            int i = tid + k * 256;
            if (i < 400) {
                int cc = i / 100, rem = i - cc * 100;
                int r = rem / 10, pi = rem - r * 10;
                int gh = h0 - 1 + r;
                int gw0 = w0 - 4 + pi * 4;
                bool ok = (gh >= 0 && gh < Hh && gw0 >= 0 && gw0 + 4 <= Ww);
                const float* g = ok ? &in[(((size_t)b * 32 + ci0 + cc) * Hh + gh) * Ww + gw0] : in;
                cpa16(scvt(&s_in[buf][cc * 400 + r * ROWW + pi * 4]), g, ok);
            }
        }
    };
    issue(0, 0);
    CP_COMMIT();

    u64 acc[2][8];
#pragma unroll
    for (int j = 0; j < 8; ++j) {
        u64 bv = pk2(bias[ch * 16 + 2 * j], bias[ch * 16 + 2 * j + 1]);
        acc[0][j] = bv; acc[1][j] = bv;
    }

    int buf = 0;
    for (int ci0 = 0; ci0 < 32; ci0 += 4) {
        CP_WAIT0();
        __syncthreads();
        if (ci0 + 4 < 32) { issue(ci0 + 4, buf ^ 1); CP_COMMIT(); }
#pragma unroll
        for (int cc = 0; cc < 4; ++cc) {
            const float* ib = &s_in[buf][cc * 400 + (gr * 2) * ROWW + tx + 3];
            const float* wb = &s_w[(ci0 + cc) * 288];
#pragma unroll
            for (int di = 0; di < 3; ++di)
#pragma unroll
                for (int dj = 0; dj < 3; ++dj) {
                    u64 v0 = pk(ib[di * ROWW + dj]);
                    u64 v1 = pk(ib[(di + 1) * ROWW + dj]);
                    const u64* wq = (const u64*)(wb + (di * 3 + dj) * 32) + ch * 8;
                    u64 q0 = wq[0], q1 = wq[1], q2 = wq[2], q3 = wq[3];
                    u64 q4 = wq[4], q5 = wq[5], q6 = wq[6], q7 = wq[7];
                    fma2(acc[0][0], v0, q0); fma2(acc[0][1], v0, q1);
                    fma2(acc[0][2], v0, q2); fma2(acc[0][3], v0, q3);
                    fma2(acc[0][4], v0, q4); fma2(acc[0][5], v0, q5);
                    fma2(acc[0][6], v0, q6); fma2(acc[0][7], v0, q7);
                    fma2(acc[1][0], v1, q0); fma2(acc[1][1], v1, q1);
                    fma2(acc[1][2], v1, q2); fma2(acc[1][3], v1, q3);
                    fma2(acc[1][4], v1, q4); fma2(acc[1][5], v1, q5);
                    fma2(acc[1][6], v1, q6); fma2(acc[1][7], v1, q7);
                }
        }
        buf ^= 1;
    }

    const size_t plane = (size_t)Hh * Ww;
#pragma unroll
    for (int p = 0; p < 2; ++p) {
        int h = h0 + gr * 2 + p;
        size_t ob = ((size_t)b * 32 + ch * 16) * plane + (size_t)h * Ww + (w0 + tx);
#pragma unroll
        for (int j = 0; j < 8; ++j) {
            float lo, hi;
            unpk(acc[p][j], lo, hi);
            out[ob + (size_t)(2 * j) * plane] = lo;
            out[ob + (size_t)(2 * j + 1) * plane] = hi;
        }
    }
}

// ---------------- composed deconv+conv interior ----------------
template <int MODE>
__global__ void __launch_bounds__(256, 3)
dconv_kernel(const float* __restrict__ in, const float* __restrict__ ck,
             const float* __restrict__ cbias, float* __restrict__ out,
             int Hi, int Wi, const float* __restrict__ orig) {
    __shared__ __align__(16) float s_in[2][640];
    __shared__ __align__(16) float s_w[2][2048];
    const int tx = threadIdx.x, ty = threadIdx.y, tid = ty * 32 + tx;
    const int c0 = blockIdx.x * 32, a0 = blockIdx.y * 2;
    const int b = blockIdx.z;

    auto issue = [&](int ci0, int buf) {
        const float* kw = ck + (size_t)ci0 * 512;
#pragma unroll
        for (int k = 0; k < 3; ++k) {
            int i = tid + k * 256;
            if (i < 160) {
                int cc = i / 40, rem = i - cc * 40;
                int r = rem / 10, pi = rem - r * 10;
                int gh = a0 - 1 + r;
                int gw0 = c0 - 4 + pi * 4;
                bool ok = (gh >= 0 && gh < Hi && gw0 >= 0 && gw0 + 4 <= Wi);
                const float* g = ok ? &in[(((size_t)b * 32 + ci0 + cc) * Hi + gh) * Wi + gw0] : in;
                cpa16(scvt(&s_in[buf][cc * 160 + r * 40 + pi * 4]), g, ok);
            } else if (i < 672) {
                int j = i - 160;
                cpa16f(scvt(&s_w[buf][j * 4]), kw + j * 4);
            }
        }
    };
    issue(0, 0);
    CP_COMMIT();

    u64 acc[4][2][2];
#pragma unroll
    for (int pr = 0; pr < 2; ++pr) {
        u64 bv = pk2(cbias[ty * 4 + 2 * pr], cbias[ty * 4 + 2 * pr + 1]);
#pragma unroll
        for (int r = 0; r < 4; ++r) { acc[r][0][pr] = bv; acc[r][1][pr] = bv; }
    }

    int buf = 0;
    for (int ci0 = 0; ci0 < 32; ci0 += 4) {
        CP_WAIT0();
        __syncthreads();
        if (ci0 + 4 < 32) { issue(ci0 + 4, buf ^ 1); CP_COMMIT(); }
#pragma unroll
        for (int cc = 0; cc < 4; ++cc) {
            const float* ib = &s_in[buf][cc * 160 + tx + 3];
            u64 vpk[4][3];
#pragma unroll
            for (int r4 = 0; r4 < 4; ++r4)
#pragma unroll
                for (int dc = 0; dc < 3; ++dc)
                    vpk[r4][dc] = pk(ib[r4 * 40 + dc]);
            const float* wb = &s_w[buf][cc * 512];
#pragma unroll
            for (int ph = 0; ph < 2; ++ph)
#pragma unroll
                for (int pw = 0; pw < 2; ++pw)
#pragma unroll
                    for (int r = 0; r < 2; ++r)
#pragma unroll
                        for (int c = 0; c < 2; ++c) {
                            const u64* wq = (const u64*)(wb + ((ph * 2 + pw) * 4 + r * 2 + c) * 32) + ty * 2;
                            u64 q0 = wq[0], q1 = wq[1];
#pragma unroll
                            for (int half = 0; half < 2; ++half) {
                                u64 v = vpk[half + ph + r][pw + c];
                                fma2(acc[half * 2 + ph][pw][0], v, q0);
                                fma2(acc[half * 2 + ph][pw][1], v, q1);
                            }
                        }
        }
        buf ^= 1;
    }

    const int Ho = 2 * Hi, Wo = 2 * Wi;
    const size_t plane = (size_t)Ho * Wo;
    const int wq0 = 2 * (c0 + tx);
#pragma unroll
    for (int row = 0; row < 4; ++row) {
        int h = 2 * a0 + row;
        if (h < 1 || h >= Ho - 1) continue;
#pragma unroll
        for (int pr = 0; pr < 2; ++pr) {
            float p0l, p0h, p1l, p1h;
            unpk(acc[row][0][pr], p0l, p0h);
            unpk(acc[row][1][pr], p1l, p1h);
            size_t ob = ((size_t)(b * 32 + ty * 4 + 2 * pr)) * plane + (size_t)h * Wo + wq0;
            if (wq0 == 0) {
                float v0 = p1l, v1 = p1h;
                if (MODE == 2) { v0 *= orig[ob + 1]; v1 *= orig[ob + plane + 1]; }
                out[ob + 1] = v0;
                out[ob + plane + 1] = v1;
            } else if (wq0 == Wo - 2) {
                float v0 = p0l, v1 = p0h;
                if (MODE == 2) { v0 *= orig[ob]; v1 *= orig[ob + plane]; }
                out[ob] = v0;
                out[ob + plane] = v1;
            } else {
                float2 f0 = make_float2(p0l, p1l);
                float2 f1 = make_float2(p0h, p1h);
                if (MODE == 2) {
                    float2 g0 = *(const float2*)(orig + ob);
                    float2 g1 = *(const float2*)(orig + ob + plane);
                    f0.x *= g0.x; f0.y *= g0.y;
                    f1.x *= g1.x; f1.y *= g1.y;
                }
                *(float2*)(out + ob) = f0;
                *(float2*)(out + ob + plane) = f1;
            }
        }
    }
}

// ---------------- composed stage border: 1-px output frame ----------------
template <int MODE>
__global__ void __launch_bounds__(256, 2)
bconv_kernel(const float* __restrict__ in, const float* __restrict__ dw,
             const float* __restrict__ db, const float* __restrict__ cw,
             const float* __restrict__ cb, float* __restrict__ out,
             int Hi, int Wi, const float* __restrict__ orig) {
    __shared__ float s_dw[4096];
    __shared__ float s_cw[9216];
    __shared__ float s_db[32];
    const int tid = threadIdx.x;
    const int b = blockIdx.y;
    const int Ho = 2 * Hi, Wo = 2 * Wi;
    const int npix = 2 * Wo + 2 * (Ho - 2);
    const int px = blockIdx.x * 64 + (tid >> 2);
    const int cg = tid & 3;

    for (int i = tid; i < 4096; i += 256) {
        int m = i >> 7, rem = i & 127;
        int pp = (rem >> 6) & 1, qq = (rem >> 5) & 1, ci = rem & 31;
        s_dw[i] = dw[(((size_t)ci * 32 + m) * 2 + pp) * 2 + qq];
    }
    for (int i = tid; i < 9216; i += 256) {
        int tap = i >> 10, rem = i & 1023;
        int m = rem >> 5, co = rem & 31;
        s_cw[i] = cw[((size_t)co * 32 + m) * 9 + tap];
    }
    if (tid < 32) s_db[tid] = db[tid];
    __syncthreads();

    if (px >= npix) return;
    int t = px;
    int h, w;
    if (t < Wo) { h = 0; w = t; }
    else if (t < 2 * Wo) { h = Ho - 1; w = t - Wo; }
    else { int t2 = t - 2 * Wo; h = 1 + (t2 >> 1); w = (t2 & 1) ? (Wo - 1) : 0; }

    float acc[8];
#pragma unroll
    for (int j = 0; j < 8; ++j) acc[j] = cb[cg * 8 + j];

    for (int di = 0; di < 3; ++di)
        for (int dj = 0; dj < 3; ++dj) {
            int p = h - 1 + di, q = w - 1 + dj;
            if (p < 0 || p >= Ho || q < 0 || q >= Wo) continue;
            int ip = p >> 1, pp = p & 1, iq = q >> 1, qq = q & 1;
            float inv[32];
#pragma unroll
            for (int ci = 0; ci < 32; ++ci)
                inv[ci] = in[((size_t)(b * 32 + ci) * Hi + ip) * Wi + iq];
            const float* dwb = &s_dw[(pp * 2 + qq) * 32];
            const float* cwt = &s_cw[(di * 3 + dj) * 1024 + cg * 8];
#pragma unroll 4
            for (int m = 0; m < 32; ++m) {
                float t1m = s_db[m];
#pragma unroll
                for (int ci = 0; ci < 32; ++ci) t1m += inv[ci] * dwb[m * 128 + ci];
                const float* cwm = cwt + m * 32;
#pragma unroll
                for (int j = 0; j < 8; ++j) acc[j] += t1m * cwm[j];
            }
        }

    {
        const size_t plane = (size_t)Ho * Wo;
        size_t ob = ((size_t)(b * 32 + cg * 8)) * plane + (size_t)h * Wo + w;
#pragma unroll
        for (int j = 0; j < 8; ++j) {
            float v = acc[j];
            if (MODE == 2) v *= orig[ob + (size_t)j * plane];
            out[ob + (size_t)j * plane] = v;
        }
    }
}

// ---------------- host launch ----------------
extern "C" void kernel_launch(void* const* d_in, const int* in_sizes, int n_in,
                              void* d_out, int out_size) {
    const float* x = (const float*)d_in[0];
    const float* w1 = (const float*)d_in[1];   const float* b1 = (const float*)d_in[2];
    const float* w2 = (const float*)d_in[3];   const float* b2 = (const float*)d_in[4];
    const float* w3 = (const float*)d_in[5];   const float* b3 = (const float*)d_in[6];
    const float* w4 = (const float*)d_in[7];   const float* b4 = (const float*)d_in[8];
    const float* w5 = (const float*)d_in[9];   const float* b5 = (const float*)d_in[10];
    const float* w6 = (const float*)d_in[11];  const float* b6 = (const float*)d_in[12];
    const float* w7 = (const float*)d_in[13];  const float* b7 = (const float*)d_in[14];
    const float* dw1 = (const float*)d_in[15]; const float* db1 = (const float*)d_in[16];
    const float* dw2 = (const float*)d_in[17]; const float* db2 = (const float*)d_in[18];
    const float* dw3 = (const float*)d_in[19]; const float* db3 = (const float*)d_in[20];
    float* outp = (float*)d_out;

    void* p;
    cudaGetSymbolAddress(&p, g_s1);   float* s1 = (float*)p;
    cudaGetSymbolAddress(&p, g_s2);   float* s2 = (float*)p;
    cudaGetSymbolAddress(&p, g_q1);   float* q1 = (float*)p;
    cudaGetSymbolAddress(&p, g_q2);   float* q2 = (float*)p;
    cudaGetSymbolAddress(&p, g_e1);   float* e1 = (float*)p;
    cudaGetSymbolAddress(&p, g_e2);   float* e2 = (float*)p;
    cudaGetSymbolAddress(&p, g_w3x3); float* wt = (float*)p;
    cudaGetSymbolAddress(&p, g_ck);   float* ckp = (float*)p;
    cudaGetSymbolAddress(&p, g_cb);   float* cbp = (float*)p;

    dim3 blk(32, 8);

    // stats + keff first so conv1_5x5 stays the 4th launch (ncu capture slot)
    stats_op_kernel<<<dim3(16, 16, B_ * C_), blk>>>(x);
    stats2_kernel<<<21, 256>>>(w1);
    keff_kernel<<<dim3(B_, 33), 32>>>(w1, b1);
    conv1_5x5_kernel<<<dim3(8, 64, B_), blk>>>(x, s1);
    conv1_strip_kernel<<<dim3(64, B_), blk>>>(x, w1, b1, s1);

    // remaining weight prep
    prep_w_kernel<<<3, 256>>>(w2, w3, w4);
    ck_kernel<<<dim3(33, 3), 32>>>(dw1, db1, w5, b5, dw2, db2, w6, b6, dw3, db3, w7, b7);

    // conv2 + pool: s1 -> q1 (128^2), 2x2 px/thread
    conv3x3p_kernel<<<dim3(4, 32, B_), blk>>>(s1, wt + 0 * 9216, b2, q1, 256, 256);
    // conv3 + pool: q1 -> e1 (64^2)
    conv3x3p_kernel<<<dim3(2, 16, B_), blk>>>(q1, wt + 1 * 9216, b3, e1, 128, 128);
    // conv4: e1 -> e2 (64^2)
    conv3x3_kernel<<<dim3(2, 8, B_), blk>>>(e1, wt + 2 * 9216, b4, e2, 64, 64);

    // stage1: composed deconv1+conv5: e2 (64^2) -> q2 (128^2)
    bconv_kernel<0><<<dim3(8, B_), 256>>>(e2, dw1, db1, w5, b5, q2, 64, 64, nullptr);
    dconv_kernel<0><<<dim3(2, 32, B_), blk>>>(e2, ckp + 0 * 16384, cbp + 0, q2, 64, 64, nullptr);
    // stage2: composed deconv2+conv6: q2 (128^2) -> s2 (256^2)
    bconv_kernel<0><<<dim3(16, B_), 256>>>(q2, dw2, db2, w6, b6, s2, 128, 128, nullptr);
    dconv_kernel<0><<<dim3(4, 64, B_), blk>>>(q2, ckp + 1 * 16384, cbp + 32, s2, 128, 128, nullptr);
    // stage3: composed deconv3+conv7 (+ orig mult): s2 (256^2) -> out (512^2)
    bconv_kernel<2><<<dim3(32, B_), 256>>>(s2, dw3, db3, w7, b7, outp, 256, 256, x);
    dconv_kernel<2><<<dim3(8, 128, B_), blk>>>(s2, ckp + 2 * 16384, cbp + 64, outp, 256, 256, x);
}